// round 10
// baseline (speedup 1.0000x reference)
#include <cuda_runtime.h>
#include <cuda_bf16.h>
#include <math.h>
#include <cstdint>

// ---------------------------------------------------------------------------
// Shapes
// ---------------------------------------------------------------------------
#define BATCH   2048
#define NTOK    64
#define DIM     192
#define HEADS   6
#define HD      32
#define QKVC    576
#define NPOS    343
#define CPBH    512
#define NW      64
#define MROWS   (BATCH * NTOK)      // 131072

// ---------------------------------------------------------------------------
// Scratch (device-code-only references!)
// ---------------------------------------------------------------------------
__device__ float g_qkv[(size_t)BATCH * 3 * HEADS * NTOK * HD];
__device__ float g_attn[(size_t)MROWS * DIM];
__device__ __align__(16) __nv_bfloat16 g_wqh[QKVC * DIM];
__device__ __align__(16) __nv_bfloat16 g_wql[QKVC * DIM];
__device__ __align__(16) __nv_bfloat16 g_wph[DIM * DIM];
__device__ __align__(16) __nv_bfloat16 g_wpl[DIM * DIM];
__device__ float g_table[NPOS * HEADS];
__device__ float g_bias[HEADS * NTOK * NTOK];
__device__ float g_bm[(size_t)NW * HEADS * NTOK * NTOK];

// ---------------------------------------------------------------------------
// helpers
// ---------------------------------------------------------------------------
__device__ __forceinline__ uint32_t smem_u32(const void* p) {
    uint32_t a;
    asm("{ .reg .u64 t; cvta.to.shared.u64 t, %1; cvt.u32.u64 %0, t; }" : "=r"(a) : "l"(p));
    return a;
}
__device__ __forceinline__ void ldsm_x4(uint32_t addr, uint32_t& r0, uint32_t& r1,
                                        uint32_t& r2, uint32_t& r3) {
    asm volatile("ldmatrix.sync.aligned.m8n8.x4.shared.b16 {%0,%1,%2,%3}, [%4];"
                 : "=r"(r0), "=r"(r1), "=r"(r2), "=r"(r3) : "r"(addr));
}
__device__ __forceinline__ void mma16816(float* c, uint32_t a0, uint32_t a1,
                                         uint32_t a2, uint32_t a3,
                                         uint32_t b0, uint32_t b1) {
    asm volatile("mma.sync.aligned.m16n8k16.row.col.f32.bf16.bf16.f32 "
                 "{%0,%1,%2,%3}, {%4,%5,%6,%7}, {%8,%9}, {%0,%1,%2,%3};"
                 : "+f"(c[0]), "+f"(c[1]), "+f"(c[2]), "+f"(c[3])
                 : "r"(a0), "r"(a1), "r"(a2), "r"(a3), "r"(b0), "r"(b1));
}
__device__ __forceinline__ uint32_t pk_bf16(float x0, float x1) {
    __nv_bfloat162 t = __floats2bfloat162_rn(x0, x1);
    return *(uint32_t*)&t;
}
__device__ __forceinline__ void cp_async16(uint32_t dst, const void* src) {
    asm volatile("cp.async.ca.shared.global [%0], [%1], 16;"
                 :: "r"(dst), "l"(src) : "memory");
}
__device__ __forceinline__ void cp_commit() {
    asm volatile("cp.async.commit_group;" ::: "memory");
}
template <int N>
__device__ __forceinline__ void cp_wait() {
    asm volatile("cp.async.wait_group %0;" :: "n"(N) : "memory");
}

// ---------------------------------------------------------------------------
// weight split-conversion: WHICH 0 = qkv_w, 1 = proj_w
// ---------------------------------------------------------------------------
template <int WHICH>
__global__ void conv_w_kernel(const float* __restrict__ src, int nElem)
{
    __nv_bfloat16* hi = (WHICH == 0) ? g_wqh : g_wph;
    __nv_bfloat16* lo = (WHICH == 0) ? g_wql : g_wpl;
    int base = (blockIdx.x * blockDim.x + threadIdx.x) * 8;
    if (base >= nElem) return;
    float4 v0 = *(const float4*)(src + base);
    float4 v1 = *(const float4*)(src + base + 4);
    float v[8] = {v0.x, v0.y, v0.z, v0.w, v1.x, v1.y, v1.z, v1.w};
    __align__(16) __nv_bfloat16 h8[8], l8[8];
#pragma unroll
    for (int i = 0; i < 8; ++i) {
        __nv_bfloat16 h = __float2bfloat16(v[i]);
        h8[i] = h;
        l8[i] = __float2bfloat16(v[i] - __bfloat162float(h));
    }
    *(uint4*)(hi + base) = *(uint4*)h8;
    *(uint4*)(lo + base) = *(uint4*)l8;
}

// ---------------------------------------------------------------------------
// GEMM: 64-row CTA, 128 threads (4 warps, 2Mx2N, warp 32x32), 2 CTAs/SM.
// A (64x192) resident in smem hi/lo; B chunks (64x192) single-buffered via
// cp.async; fragment-reuse 3-pass split-bf16 mma; epilogue overlaps next
// chunk's cp.async.
// ---------------------------------------------------------------------------
#define PITCHB 400
#define SM_AHI 0
#define SM_ALO (64 * PITCHB)                  // 25600
#define SM_BHI (2 * 64 * PITCHB)              // 51200
#define SM_BLO (3 * 64 * PITCHB)              // 76800
#define SM_GEMM_BYTES (4 * 64 * PITCHB)       // 102400

template <int MODE>
__global__ void __launch_bounds__(128, 2)
gemm_mma_kernel(const float* __restrict__ Ain,
                const float* __restrict__ bias, float* __restrict__ out)
{
    constexpr int NC = (MODE == 0) ? 9 : 3;
    const float* __restrict__ A = (MODE == 0) ? Ain : g_attn;
    const __nv_bfloat16* __restrict__ Whi = (MODE == 0) ? g_wqh : g_wph;
    const __nv_bfloat16* __restrict__ Wlo = (MODE == 0) ? g_wql : g_wpl;

    extern __shared__ __align__(16) char sm[];
    const int tid = threadIdx.x;
    const int wid = tid >> 5;
    const int lane = tid & 31;
    const int rowBase = blockIdx.x * 64;
    const uint32_t smBase = smem_u32(sm);

    // ---- prefetch B chunk 0 (overlaps with A load/split) ----
#pragma unroll
    for (int i = tid; i < 64 * 24; i += 128) {
        int r = i / 24, c = i % 24;
        size_t gg = (size_t)r * DIM + c * 8;
        cp_async16(smBase + SM_BHI + r * PITCHB + c * 16, Whi + gg);
        cp_async16(smBase + SM_BLO + r * PITCHB + c * 16, Wlo + gg);
    }
    cp_commit();

    // ---- load A fp32 -> split to smem hi/lo (64 x 192) ----
#pragma unroll
    for (int i = tid; i < 64 * 48; i += 128) {
        int r = i / 48, c4 = i % 48;
        float4 v = *(const float4*)(A + (size_t)(rowBase + r) * DIM + c4 * 4);
        float vv[4] = {v.x, v.y, v.z, v.w};
        __align__(8) __nv_bfloat16 h4[4], l4[4];
#pragma unroll
        for (int q = 0; q < 4; ++q) {
            __nv_bfloat16 h = __float2bfloat16(vv[q]);
            h4[q] = h;
            l4[q] = __float2bfloat16(vv[q] - __bfloat162float(h));
        }
        *(uint2*)(sm + SM_AHI + r * PITCHB + c4 * 8) = *(uint2*)h4;
        *(uint2*)(sm + SM_ALO + r * PITCHB + c4 * 8) = *(uint2*)l4;
    }

    const int warpM = wid >> 1;    // 0..1
    const int warpN = wid & 1;     // 0..1
    const int lrow = lane & 7;
    const int lmat = lane >> 3;

    const uint32_t aOff = (uint32_t)((warpM * 32 + lrow + (lmat & 1) * 8) * PITCHB
                                     + (lmat >> 1) * 16);
    const uint32_t bOff = (uint32_t)((warpN * 32 + lrow + (lmat >> 1) * 8) * PITCHB
                                     + (lmat & 1) * 16);
    const uint32_t aHiB = smBase + SM_AHI + aOff;
    const uint32_t aLoB = smBase + SM_ALO + aOff;
    const uint32_t bHiT = smBase + SM_BHI + bOff;
    const uint32_t bLoT = smBase + SM_BLO + bOff;
    const int g = lane >> 2, tig = lane & 3;

    for (int cc = 0; cc < NC; ++cc) {
        cp_wait<0>();
        __syncthreads();           // B(cc) visible to all warps

        float c[2][4][4] = {};
#pragma unroll
        for (int k = 0; k < 12; ++k) {
            uint32_t ah[2][4], al[2][4];
            uint32_t bh[4], bh2[4], bl[4], bl2[4];
            ldsm_x4(aHiB + k * 32,               ah[0][0], ah[0][1], ah[0][2], ah[0][3]);
            ldsm_x4(aHiB + 16 * PITCHB + k * 32, ah[1][0], ah[1][1], ah[1][2], ah[1][3]);
            ldsm_x4(aLoB + k * 32,               al[0][0], al[0][1], al[0][2], al[0][3]);
            ldsm_x4(aLoB + 16 * PITCHB + k * 32, al[1][0], al[1][1], al[1][2], al[1][3]);
            ldsm_x4(bHiT + k * 32,               bh[0], bh[1], bh[2], bh[3]);
            ldsm_x4(bHiT + 16 * PITCHB + k * 32, bh2[0], bh2[1], bh2[2], bh2[3]);
            ldsm_x4(bLoT + k * 32,               bl[0], bl[1], bl[2], bl[3]);
            ldsm_x4(bLoT + 16 * PITCHB + k * 32, bl2[0], bl2[1], bl2[2], bl2[3]);
#pragma unroll
            for (int mi = 0; mi < 2; ++mi) {
                // pass 0: Ahi x Bhi
                mma16816(c[mi][0], ah[mi][0], ah[mi][1], ah[mi][2], ah[mi][3], bh[0], bh[1]);
                mma16816(c[mi][1], ah[mi][0], ah[mi][1], ah[mi][2], ah[mi][3], bh[2], bh[3]);
                mma16816(c[mi][2], ah[mi][0], ah[mi][1], ah[mi][2], ah[mi][3], bh2[0], bh2[1]);
                mma16816(c[mi][3], ah[mi][0], ah[mi][1], ah[mi][2], ah[mi][3], bh2[2], bh2[3]);
                // pass 1: Ahi x Blo
                mma16816(c[mi][0], ah[mi][0], ah[mi][1], ah[mi][2], ah[mi][3], bl[0], bl[1]);
                mma16816(c[mi][1], ah[mi][0], ah[mi][1], ah[mi][2], ah[mi][3], bl[2], bl[3]);
                mma16816(c[mi][2], ah[mi][0], ah[mi][1], ah[mi][2], ah[mi][3], bl2[0], bl2[1]);
                mma16816(c[mi][3], ah[mi][0], ah[mi][1], ah[mi][2], ah[mi][3], bl2[2], bl2[3]);
                // pass 2: Alo x Bhi
                mma16816(c[mi][0], al[mi][0], al[mi][1], al[mi][2], al[mi][3], bh[0], bh[1]);
                mma16816(c[mi][1], al[mi][0], al[mi][1], al[mi][2], al[mi][3], bh[2], bh[3]);
                mma16816(c[mi][2], al[mi][0], al[mi][1], al[mi][2], al[mi][3], bh2[0], bh2[1]);
                mma16816(c[mi][3], al[mi][0], al[mi][1], al[mi][2], al[mi][3], bh2[2], bh2[3]);
            }
        }

        __syncthreads();           // B(cc) fully consumed by all warps

        // ---- prefetch B(cc+1) into the (now free) buffer ----
        if (cc + 1 < NC) {
            const int colN = (cc + 1) * 64;
#pragma unroll
            for (int i = tid; i < 64 * 24; i += 128) {
                int r = i / 24, c2 = i % 24;
                size_t gg = (size_t)(colN + r) * DIM + c2 * 8;
                cp_async16(smBase + SM_BHI + r * PITCHB + c2 * 16, Whi + gg);
                cp_async16(smBase + SM_BLO + r * PITCHB + c2 * 16, Wlo + gg);
            }
            cp_commit();
        }

        // ---- epilogue (overlaps with async B arrival) ----
        const int colBase = cc * 64;
#pragma unroll
        for (int mi = 0; mi < 2; ++mi) {
#pragma unroll
            for (int ni = 0; ni < 4; ++ni) {
                int row0 = rowBase + warpM * 32 + mi * 16 + g;
                int col = colBase + warpN * 32 + ni * 8 + tig * 2;
                float b0 = bias[col], b1 = bias[col + 1];
#pragma unroll
                for (int rr = 0; rr < 2; ++rr) {
                    int row = row0 + rr * 8;
                    float2 val = make_float2(c[mi][ni][rr * 2] + b0, c[mi][ni][rr * 2 + 1] + b1);
                    if (MODE == 0) {
                        int b = row >> 6, n = row & 63;
                        int which = col / DIM;
                        int rem = col - which * DIM;
                        int h = rem >> 5, d = rem & 31;
                        size_t idx = ((((size_t)b * 3 + which) * HEADS + h) * NTOK + n) * HD + d;
                        *(float2*)(g_qkv + idx) = val;
                    } else {
                        *(float2*)(out + (size_t)row * DIM + col) = val;
                    }
                }
            }
        }
    }
}

// ---------------------------------------------------------------------------
// CPB MLP + bias gather + bias/mask combine
// ---------------------------------------------------------------------------
__global__ void cpb_table_kernel(const float* __restrict__ rpb,
                                 const float* __restrict__ w1,
                                 const float* __restrict__ b1,
                                 const float* __restrict__ w2)
{
    __shared__ float red[4][HEADS];
    const int p = blockIdx.x;
    const int tid = threadIdx.x;
    float r0 = rpb[p * 3 + 0], r1 = rpb[p * 3 + 1], r2 = rpb[p * 3 + 2];
    float acc[HEADS] = {};
    for (int j = tid; j < CPBH; j += 128) {
        float hv = fmaf(w1[j * 3 + 0], r0, fmaf(w1[j * 3 + 1], r1, fmaf(w1[j * 3 + 2], r2, b1[j])));
        hv = fmaxf(hv, 0.f);
#pragma unroll
        for (int h = 0; h < HEADS; ++h) acc[h] = fmaf(hv, w2[h * CPBH + j], acc[h]);
    }
#pragma unroll
    for (int h = 0; h < HEADS; ++h)
#pragma unroll
        for (int s = 16; s; s >>= 1) acc[h] += __shfl_xor_sync(~0u, acc[h], s);
    if ((tid & 31) == 0) {
#pragma unroll
        for (int h = 0; h < HEADS; ++h) red[tid >> 5][h] = acc[h];
    }
    __syncthreads();
    if (tid < HEADS)
        g_table[p * HEADS + tid] = red[0][tid] + red[1][tid] + red[2][tid] + red[3][tid];
}

__global__ void bias_gather_kernel(const int* __restrict__ rpb_idx)
{
    int idx = blockIdx.x * blockDim.x + threadIdx.x;
    if (idx >= HEADS * NTOK * NTOK) return;
    int h = idx / (NTOK * NTOK);
    int ij = idx % (NTOK * NTOK);
    float t = g_table[rpb_idx[ij] * HEADS + h];
    g_bias[idx] = 16.f / (1.f + expf(-t));
}

__global__ void bm_kernel(const float* __restrict__ mask)
{
    int w = blockIdx.x, h = blockIdx.y;
    const float* mp = mask + (size_t)w * NTOK * NTOK;
    const float* bp = g_bias + (size_t)h * NTOK * NTOK;
    float* o = g_bm + ((size_t)(w * HEADS + h)) * NTOK * NTOK;
    for (int ij = threadIdx.x; ij < NTOK * NTOK; ij += 256)
        o[ij] = bp[ij] + mp[ij];
}

// ---------------------------------------------------------------------------
// tensor-core attention (unchanged from round 7/9)
// ---------------------------------------------------------------------------
#define QP  80
#define VTP 144

__global__ void __launch_bounds__(128)
attn_mma_kernel(const float* __restrict__ logit_scale)
{
    __shared__ __align__(16) char s_qhi[64 * QP], s_qlo[64 * QP];
    __shared__ __align__(16) char s_khi[64 * QP], s_klo[64 * QP];
    __shared__ __align__(16) char s_vhi[32 * VTP], s_vlo[32 * VTP];

    const int b = blockIdx.x;
    const int h = blockIdx.y;
    const int tid = threadIdx.x;

    const float scale = __expf(fminf(logit_scale[h], 4.60517018599f));

    const float* qp = g_qkv + ((((size_t)b * 3 + 0) * HEADS + h) * NTOK) * HD;
    const float* kp = g_qkv + ((((size_t)b * 3 + 1) * HEADS + h) * NTOK) * HD;
    const float* vp = g_qkv + ((((size_t)b * 3 + 2) * HEADS + h) * NTOK) * HD;

    {
        const int row = tid >> 1;
        const int half = (tid & 1) * 16;

        float qv[16];
        {
            float4 f0 = *(const float4*)(qp + row * HD + half);
            float4 f1 = *(const float4*)(qp + row * HD + half + 4);
            float4 f2 = *(const float4*)(qp + row * HD + half + 8);
            float4 f3 = *(const float4*)(qp + row * HD + half + 12);
            qv[0]=f0.x; qv[1]=f0.y; qv[2]=f0.z; qv[3]=f0.w;
            qv[4]=f1.x; qv[5]=f1.y; qv[6]=f1.z; qv[7]=f1.w;
            qv[8]=f2.x; qv[9]=f2.y; qv[10]=f2.z; qv[11]=f2.w;
            qv[12]=f3.x; qv[13]=f3.y; qv[14]=f3.z; qv[15]=f3.w;
            float ps = 0.f;
#pragma unroll
            for (int i = 0; i < 16; ++i) ps = fmaf(qv[i], qv[i], ps);
            float tot = ps + __shfl_xor_sync(~0u, ps, 1);
            float s = scale / fmaxf(sqrtf(tot), 1e-12f);
            __align__(16) __nv_bfloat16 h16[16], l16[16];
#pragma unroll
            for (int i = 0; i < 16; ++i) {
                float v = qv[i] * s;
                __nv_bfloat16 hh = __float2bfloat16(v);
                h16[i] = hh;
                l16[i] = __float2bfloat16(v - __bfloat162float(hh));
            }
            *(uint4*)(s_qhi + row * QP + half * 2)      = *(uint4*)h16;
            *(uint4*)(s_qhi + row * QP + half * 2 + 16) = *(uint4*)(h16 + 8);
            *(uint4*)(s_qlo + row * QP + half * 2)      = *(uint4*)l16;
            *(uint4*)(s_qlo + row * QP + half * 2 + 16) = *(uint4*)(l16 + 8);
        }
        {
            float4 f0 = *(const float4*)(kp + row * HD + half);
            float4 f1 = *(const float4*)(kp + row * HD + half + 4);
            float4 f2 = *(const float4*)(kp + row * HD + half + 8);
            float4 f3 = *(const float4*)(kp + row * HD + half + 12);
            float kv[16] = {f0.x,f0.y,f0.z,f0.w, f1.x,f1.y,f1.z,f1.w,
                            f2.x,f2.y,f2.z,f2.w, f3.x,f3.y,f3.z,f3.w};
            float ps = 0.f;
#pragma unroll
            for (int i = 0; i < 16; ++i) ps = fmaf(kv[i], kv[i], ps);
            float tot = ps + __shfl_xor_sync(~0u, ps, 1);
            float s = 1.f / fmaxf(sqrtf(tot), 1e-12f);
            __align__(16) __nv_bfloat16 h16[16], l16[16];
#pragma unroll
            for (int i = 0; i < 16; ++i) {
                float v = kv[i] * s;
                __nv_bfloat16 hh = __float2bfloat16(v);
                h16[i] = hh;
                l16[i] = __float2bfloat16(v - __bfloat162float(hh));
            }
            *(uint4*)(s_khi + row * QP + half * 2)      = *(uint4*)h16;
            *(uint4*)(s_khi + row * QP + half * 2 + 16) = *(uint4*)(h16 + 8);
            *(uint4*)(s_klo + row * QP + half * 2)      = *(uint4*)l16;
            *(uint4*)(s_klo + row * QP + half * 2 + 16) = *(uint4*)(l16 + 8);
        }
        {
            float4 f0 = *(const float4*)(vp + row * HD + half);
            float4 f1 = *(const float4*)(vp + row * HD + half + 4);
            float4 f2 = *(const float4*)(vp + row * HD + half + 8);
            float4 f3 = *(const float4*)(vp + row * HD + half + 12);
            float vv[16] = {f0.x,f0.y,f0.z,f0.w, f1.x,f1.y,f1.z,f1.w,
                            f2.x,f2.y,f2.z,f2.w, f3.x,f3.y,f3.z,f3.w};
#pragma unroll
            for (int i = 0; i < 16; ++i) {
                int d = half + i;
                __nv_bfloat16 hh = __float2bfloat16(vv[i]);
                *(__nv_bfloat16*)(s_vhi + d * VTP + row * 2) = hh;
                *(__nv_bfloat16*)(s_vlo + d * VTP + row * 2) =
                    __float2bfloat16(vv[i] - __bfloat162float(hh));
            }
        }
    }
    __syncthreads();

    const int w = tid >> 5;
    const int lane = tid & 31;
    const int lrow = lane & 7;
    const int lmat = lane >> 3;
    const int g = lane >> 2;
    const int tig = lane & 3;

    const uint32_t aOff = (uint32_t)((w * 16 + lrow + (lmat & 1) * 8) * QP + (lmat >> 1) * 16);
    const uint32_t bOff = (uint32_t)((lrow + (lmat >> 1) * 8) * QP + (lmat & 1) * 16);
    const uint32_t qB[3] = { smem_u32(s_qhi), smem_u32(s_qhi), smem_u32(s_qlo) };
    const uint32_t kB[3] = { smem_u32(s_khi), smem_u32(s_klo), smem_u32(s_khi) };

    float c[8][4] = {};
#pragma unroll
    for (int p = 0; p < 3; ++p) {
#pragma unroll
        for (int kt = 0; kt < 2; ++kt) {
            uint32_t a[4];
            ldsm_x4(qB[p] + aOff + kt * 32, a[0], a[1], a[2], a[3]);
#pragma unroll
            for (int nt = 0; nt < 4; ++nt) {
                uint32_t bb[4];
                ldsm_x4(kB[p] + bOff + nt * 16 * QP + kt * 32, bb[0], bb[1], bb[2], bb[3]);
                mma16816(c[nt * 2],     a[0], a[1], a[2], a[3], bb[0], bb[1]);
                mma16816(c[nt * 2 + 1], a[0], a[1], a[2], a[3], bb[2], bb[3]);
            }
        }
    }

    const float* bmp = g_bm + ((size_t)((b & (NW - 1)) * HEADS + h)) * NTOK * NTOK;
    const int r0 = w * 16 + g;
#pragma unroll
    for (int ni = 0; ni < 8; ++ni) {
        int col = ni * 8 + tig * 2;
        float2 b0 = *(const float2*)(bmp + r0 * NTOK + col);
        float2 b1 = *(const float2*)(bmp + (r0 + 8) * NTOK + col);
        c[ni][0] += b0.x; c[ni][1] += b0.y;
        c[ni][2] += b1.x; c[ni][3] += b1.y;
    }
    float mx0 = -3.4e38f, mx1 = -3.4e38f;
#pragma unroll
    for (int ni = 0; ni < 8; ++ni) {
        mx0 = fmaxf(mx0, fmaxf(c[ni][0], c[ni][1]));
        mx1 = fmaxf(mx1, fmaxf(c[ni][2], c[ni][3]));
    }
    mx0 = fmaxf(mx0, __shfl_xor_sync(~0u, mx0, 1));
    mx0 = fmaxf(mx0, __shfl_xor_sync(~0u, mx0, 2));
    mx1 = fmaxf(mx1, __shfl_xor_sync(~0u, mx1, 1));
    mx1 = fmaxf(mx1, __shfl_xor_sync(~0u, mx1, 2));
    float s0 = 0.f, s1 = 0.f;
#pragma unroll
    for (int ni = 0; ni < 8; ++ni) {
        c[ni][0] = __expf(c[ni][0] - mx0); s0 += c[ni][0];
        c[ni][1] = __expf(c[ni][1] - mx0); s0 += c[ni][1];
        c[ni][2] = __expf(c[ni][2] - mx1); s1 += c[ni][2];
        c[ni][3] = __expf(c[ni][3] - mx1); s1 += c[ni][3];
    }
    s0 += __shfl_xor_sync(~0u, s0, 1); s0 += __shfl_xor_sync(~0u, s0, 2);
    s1 += __shfl_xor_sync(~0u, s1, 1); s1 += __shfl_xor_sync(~0u, s1, 2);
    const float i0 = 1.f / s0, i1 = 1.f / s1;
#pragma unroll
    for (int ni = 0; ni < 8; ++ni) {
        c[ni][0] *= i0; c[ni][1] *= i0;
        c[ni][2] *= i1; c[ni][3] *= i1;
    }

    uint32_t aH[4][4], aL[4][4];
#pragma unroll
    for (int kt = 0; kt < 4; ++kt) {
        const float* p0 = c[2 * kt];
        const float* p1 = c[2 * kt + 1];
        float v[8] = { p0[0], p0[1], p0[2], p0[3], p1[0], p1[1], p1[2], p1[3] };
        float lo[8];
#pragma unroll
        for (int i = 0; i < 8; ++i) {
            float hf = __bfloat162float(__float2bfloat16(v[i]));
            lo[i] = v[i] - hf;
        }
        aH[kt][0] = pk_bf16(v[0], v[1]); aH[kt][1] = pk_bf16(v[2], v[3]);
        aH[kt][2] = pk_bf16(v[4], v[5]); aH[kt][3] = pk_bf16(v[6], v[7]);
        aL[kt][0] = pk_bf16(lo[0], lo[1]); aL[kt][1] = pk_bf16(lo[2], lo[3]);
        aL[kt][2] = pk_bf16(lo[4], lo[5]); aL[kt][3] = pk_bf16(lo[6], lo[7]);
    }

    const uint32_t vOff = (uint32_t)((lrow + (lmat >> 1) * 8) * VTP + (lmat & 1) * 16);
    const uint32_t vB[3] = { smem_u32(s_vhi), smem_u32(s_vlo), smem_u32(s_vhi) };

    float o[4][4] = {};
#pragma unroll
    for (int p = 0; p < 3; ++p) {
        uint32_t (*aSel)[4] = (p == 2) ? aL : aH;
#pragma unroll
        for (int kt = 0; kt < 4; ++kt) {
            uint32_t b0[4], b1[4];
            ldsm_x4(vB[p] + vOff + kt * 32,            b0[0], b0[1], b0[2], b0[3]);
            ldsm_x4(vB[p] + vOff + 16 * VTP + kt * 32, b1[0], b1[1], b1[2], b1[3]);
            mma16816(o[0], aSel[kt][0], aSel[kt][1], aSel[kt][2], aSel[kt][3], b0[0], b0[1]);
            mma16816(o[1], aSel[kt][0], aSel[kt][1], aSel[kt][2], aSel[kt][3], b0[2], b0[3]);
            mma16816(o[2], aSel[kt][0], aSel[kt][1], aSel[kt][2], aSel[kt][3], b1[0], b1[1]);
            mma16816(o[3], aSel[kt][0], aSel[kt][1], aSel[kt][2], aSel[kt][3], b1[2], b1[3]);
        }
    }

    float* op = g_attn + ((size_t)b * NTOK + r0) * DIM + h * HD;
#pragma unroll
    for (int ni = 0; ni < 4; ++ni) {
        int col = ni * 8 + tig * 2;
        *(float2*)(op + col) = make_float2(o[ni][0], o[ni][1]);
        *(float2*)(op + 8 * DIM + col) = make_float2(o[ni][2], o[ni][3]);
    }
}

// ---------------------------------------------------------------------------
// Launch
// ---------------------------------------------------------------------------
extern "C" void kernel_launch(void* const* d_in, const int* in_sizes, int n_in,
                              void* d_out, int out_size)
{
    const float* x       = (const float*)d_in[0];
    const float* mask    = (const float*)d_in[1];
    const float* rpb     = (const float*)d_in[2];
    const int*   rpb_idx = (const int*)  d_in[3];
    const float* cpb_w1  = (const float*)d_in[4];
    const float* cpb_b1  = (const float*)d_in[5];
    const float* cpb_w2  = (const float*)d_in[6];
    const float* qkv_w   = (const float*)d_in[7];
    const float* qkv_b   = (const float*)d_in[8];
    const float* proj_w  = (const float*)d_in[9];
    const float* proj_b  = (const float*)d_in[10];
    const float* lscale  = (const float*)d_in[11];
    float* out = (float*)d_out;

    cudaFuncSetAttribute(gemm_mma_kernel<0>, cudaFuncAttributeMaxDynamicSharedMemorySize, SM_GEMM_BYTES);
    cudaFuncSetAttribute(gemm_mma_kernel<1>, cudaFuncAttributeMaxDynamicSharedMemorySize, SM_GEMM_BYTES);

    conv_w_kernel<0><<<(QKVC * DIM / 8 + 255) / 256, 256>>>(qkv_w, QKVC * DIM);
    conv_w_kernel<1><<<(DIM * DIM / 8 + 255) / 256, 256>>>(proj_w, DIM * DIM);

    cpb_table_kernel<<<NPOS, 128>>>(rpb, cpb_w1, cpb_b1, cpb_w2);
    bias_gather_kernel<<<(HEADS * NTOK * NTOK + 255) / 256, 256>>>(rpb_idx);
    bm_kernel<<<dim3(NW, HEADS), 256>>>(mask);

    gemm_mma_kernel<0><<<MROWS / 64, 128, SM_GEMM_BYTES>>>(x, qkv_b, nullptr);

    dim3 ga(BATCH, HEADS);
    attn_mma_kernel<<<ga, 128>>>(lscale);

    gemm_mma_kernel<1><<<MROWS / 64, 128, SM_GEMM_BYTES>>>(nullptr, proj_b, out);
}

// round 11
// speedup vs baseline: 1.0185x; 1.0185x over previous
#include <cuda_runtime.h>
#include <cuda_bf16.h>
#include <math.h>
#include <cstdint>

// ---------------------------------------------------------------------------
// Shapes
// ---------------------------------------------------------------------------
#define BATCH   2048
#define NTOK    64
#define DIM     192
#define HEADS   6
#define HD      32
#define QKVC    576
#define NPOS    343
#define CPBH    512
#define NW      64
#define MROWS   (BATCH * NTOK)      // 131072

// ---------------------------------------------------------------------------
// Scratch (device-code-only references!)
// ---------------------------------------------------------------------------
__device__ float g_qkv[(size_t)BATCH * 3 * HEADS * NTOK * HD];
__device__ __align__(16) __nv_bfloat16 g_ahi[(size_t)MROWS * DIM];  // attn out hi
__device__ __align__(16) __nv_bfloat16 g_alo[(size_t)MROWS * DIM];  // attn out lo
__device__ __align__(16) __nv_bfloat16 g_wqh[QKVC * DIM];
__device__ __align__(16) __nv_bfloat16 g_wql[QKVC * DIM];
__device__ __align__(16) __nv_bfloat16 g_wph[DIM * DIM];
__device__ __align__(16) __nv_bfloat16 g_wpl[DIM * DIM];
__device__ float g_table[NPOS * HEADS];
__device__ float g_bias[HEADS * NTOK * NTOK];
__device__ float g_bm[(size_t)NW * HEADS * NTOK * NTOK];

// ---------------------------------------------------------------------------
// helpers
// ---------------------------------------------------------------------------
__device__ __forceinline__ uint32_t smem_u32(const void* p) {
    uint32_t a;
    asm("{ .reg .u64 t; cvta.to.shared.u64 t, %1; cvt.u32.u64 %0, t; }" : "=r"(a) : "l"(p));
    return a;
}
__device__ __forceinline__ void ldsm_x4(uint32_t addr, uint32_t& r0, uint32_t& r1,
                                        uint32_t& r2, uint32_t& r3) {
    asm volatile("ldmatrix.sync.aligned.m8n8.x4.shared.b16 {%0,%1,%2,%3}, [%4];"
                 : "=r"(r0), "=r"(r1), "=r"(r2), "=r"(r3) : "r"(addr));
}
__device__ __forceinline__ void mma16816(float* c, uint32_t a0, uint32_t a1,
                                         uint32_t a2, uint32_t a3,
                                         uint32_t b0, uint32_t b1) {
    asm volatile("mma.sync.aligned.m16n8k16.row.col.f32.bf16.bf16.f32 "
                 "{%0,%1,%2,%3}, {%4,%5,%6,%7}, {%8,%9}, {%0,%1,%2,%3};"
                 : "+f"(c[0]), "+f"(c[1]), "+f"(c[2]), "+f"(c[3])
                 : "r"(a0), "r"(a1), "r"(a2), "r"(a3), "r"(b0), "r"(b1));
}
__device__ __forceinline__ uint32_t pk_bf16(float x0, float x1) {
    __nv_bfloat162 t = __floats2bfloat162_rn(x0, x1);
    return *(uint32_t*)&t;
}
__device__ __forceinline__ void cp_async16(uint32_t dst, const void* src) {
    asm volatile("cp.async.ca.shared.global [%0], [%1], 16;"
                 :: "r"(dst), "l"(src) : "memory");
}
__device__ __forceinline__ void cp_commit() {
    asm volatile("cp.async.commit_group;" ::: "memory");
}
template <int N>
__device__ __forceinline__ void cp_wait() {
    asm volatile("cp.async.wait_group %0;" :: "n"(N) : "memory");
}

// ---------------------------------------------------------------------------
// weight split-conversion: WHICH 0 = qkv_w, 1 = proj_w
// ---------------------------------------------------------------------------
template <int WHICH>
__global__ void conv_w_kernel(const float* __restrict__ src, int nElem)
{
    __nv_bfloat16* hi = (WHICH == 0) ? g_wqh : g_wph;
    __nv_bfloat16* lo = (WHICH == 0) ? g_wql : g_wpl;
    int base = (blockIdx.x * blockDim.x + threadIdx.x) * 8;
    if (base >= nElem) return;
    float4 v0 = *(const float4*)(src + base);
    float4 v1 = *(const float4*)(src + base + 4);
    float v[8] = {v0.x, v0.y, v0.z, v0.w, v1.x, v1.y, v1.z, v1.w};
    __align__(16) __nv_bfloat16 h8[8], l8[8];
#pragma unroll
    for (int i = 0; i < 8; ++i) {
        __nv_bfloat16 h = __float2bfloat16(v[i]);
        h8[i] = h;
        l8[i] = __float2bfloat16(v[i] - __bfloat162float(h));
    }
    *(uint4*)(hi + base) = *(uint4*)h8;
    *(uint4*)(lo + base) = *(uint4*)l8;
}

// ---------------------------------------------------------------------------
// GEMM (round-9 config): 128-row CTA, 8 warps (4Mx2N), A-resident,
// cp.async double-buffered B chunks, fragment-reuse 3-pass split-bf16.
// MODE 0: A = x fp32 (split in-kernel) -> scatter g_qkv.
// MODE 1: A = g_ahi/g_alo pre-split (cp.async direct) -> row-major out.
// ---------------------------------------------------------------------------
#define PITCHB 400
#define SM_AHI 0
#define SM_ALO (128 * PITCHB)                 // 51200
#define SM_B   (2 * 128 * PITCHB)             // 102400
#define SM_BUFSZ (2 * 64 * PITCHB)            // 51200 (hi+lo)
#define SM_BLO_OFF (64 * PITCHB)              // 25600
#define SM_GEMM_BYTES (SM_B + 2 * SM_BUFSZ)   // 204800

template <int MODE>
__global__ void __launch_bounds__(256, 1)
gemm_mma_kernel(const float* __restrict__ Ain,
                const float* __restrict__ bias, float* __restrict__ out)
{
    constexpr int NC = (MODE == 0) ? 9 : 3;
    const __nv_bfloat16* __restrict__ Whi = (MODE == 0) ? g_wqh : g_wph;
    const __nv_bfloat16* __restrict__ Wlo = (MODE == 0) ? g_wql : g_wpl;

    extern __shared__ __align__(16) char sm[];
    const int tid = threadIdx.x;
    const int wid = tid >> 5;
    const int lane = tid & 31;
    const int rowBase = blockIdx.x * 128;
    const uint32_t smBase = smem_u32(sm);

    // ---- prefetch B chunk 0 via cp.async (group 0) ----
    {
        const uint32_t dBase = smBase + SM_B;
#pragma unroll
        for (int i = tid; i < 64 * 24; i += 256) {
            int r = i / 24, c = i % 24;
            size_t gg = (size_t)r * DIM + c * 8;
            uint32_t d = dBase + r * PITCHB + c * 16;
            cp_async16(d, Whi + gg);
            cp_async16(d + SM_BLO_OFF, Wlo + gg);
        }
        cp_commit();
    }

    // ---- load A ----
    if (MODE == 0) {
        // fp32 -> split to smem hi/lo (synchronous; overlaps with cp.async)
#pragma unroll
        for (int i = tid; i < 128 * 48; i += 256) {
            int r = i / 48, c4 = i % 48;
            float4 v = *(const float4*)(Ain + (size_t)(rowBase + r) * DIM + c4 * 4);
            float vv[4] = {v.x, v.y, v.z, v.w};
            __align__(8) __nv_bfloat16 h4[4], l4[4];
#pragma unroll
            for (int q = 0; q < 4; ++q) {
                __nv_bfloat16 h = __float2bfloat16(vv[q]);
                h4[q] = h;
                l4[q] = __float2bfloat16(vv[q] - __bfloat162float(h));
            }
            *(uint2*)(sm + SM_AHI + r * PITCHB + c4 * 8) = *(uint2*)h4;
            *(uint2*)(sm + SM_ALO + r * PITCHB + c4 * 8) = *(uint2*)l4;
        }
    } else {
        // pre-split bf16 hi/lo via cp.async (group 1)
#pragma unroll
        for (int i = tid; i < 128 * 24; i += 256) {
            int r = i / 24, c = i % 24;
            size_t gg = (size_t)(rowBase + r) * DIM + c * 8;
            cp_async16(smBase + SM_AHI + r * PITCHB + c * 16, g_ahi + gg);
            cp_async16(smBase + SM_ALO + r * PITCHB + c * 16, g_alo + gg);
        }
        cp_commit();
    }

    const int warpM = wid >> 1;
    const int warpN = wid & 1;
    const int lrow = lane & 7;
    const int lmat = lane >> 3;

    const uint32_t aOff = (uint32_t)((warpM * 32 + lrow + (lmat & 1) * 8) * PITCHB
                                     + (lmat >> 1) * 16);
    const uint32_t bOff = (uint32_t)((warpN * 32 + lrow + (lmat >> 1) * 8) * PITCHB
                                     + (lmat & 1) * 16);
    const uint32_t aHiB = smBase + SM_AHI + aOff;
    const uint32_t aLoB = smBase + SM_ALO + aOff;
    const int g = lane >> 2, tig = lane & 3;

    for (int cc = 0; cc < NC; ++cc) {
        const int cur = cc & 1;
        // prefetch next chunk into the other buffer, then wait for current
        // (and, at cc==0 in MODE 1, for the A group committed before it)
        if (cc + 1 < NC) {
            const uint32_t dBase = smBase + SM_B + (1 - cur) * SM_BUFSZ;
            const int colN = (cc + 1) * 64;
#pragma unroll
            for (int i = tid; i < 64 * 24; i += 256) {
                int r = i / 24, c = i % 24;
                size_t gg = (size_t)(colN + r) * DIM + c * 8;
                uint32_t d = dBase + r * PITCHB + c * 16;
                cp_async16(d, Whi + gg);
                cp_async16(d + SM_BLO_OFF, Wlo + gg);
            }
            cp_commit();
            cp_wait<1>();
        } else {
            cp_wait<0>();
        }
        __syncthreads();

        const uint32_t bHiT = smBase + SM_B + cur * SM_BUFSZ + bOff;
        const uint32_t bLoT = bHiT + SM_BLO_OFF;

        float c[2][4][4] = {};
#pragma unroll
        for (int k = 0; k < 12; ++k) {
            uint32_t ah[2][4], al[2][4];
            uint32_t bh[4], bh2[4], bl[4], bl2[4];
            ldsm_x4(aHiB + k * 32,               ah[0][0], ah[0][1], ah[0][2], ah[0][3]);
            ldsm_x4(aHiB + 16 * PITCHB + k * 32, ah[1][0], ah[1][1], ah[1][2], ah[1][3]);
            ldsm_x4(aLoB + k * 32,               al[0][0], al[0][1], al[0][2], al[0][3]);
            ldsm_x4(aLoB + 16 * PITCHB + k * 32, al[1][0], al[1][1], al[1][2], al[1][3]);
            ldsm_x4(bHiT + k * 32,               bh[0], bh[1], bh[2], bh[3]);
            ldsm_x4(bHiT + 16 * PITCHB + k * 32, bh2[0], bh2[1], bh2[2], bh2[3]);
            ldsm_x4(bLoT + k * 32,               bl[0], bl[1], bl[2], bl[3]);
            ldsm_x4(bLoT + 16 * PITCHB + k * 32, bl2[0], bl2[1], bl2[2], bl2[3]);
#pragma unroll
            for (int mi = 0; mi < 2; ++mi) {
                mma16816(c[mi][0], ah[mi][0], ah[mi][1], ah[mi][2], ah[mi][3], bh[0], bh[1]);
                mma16816(c[mi][1], ah[mi][0], ah[mi][1], ah[mi][2], ah[mi][3], bh[2], bh[3]);
                mma16816(c[mi][2], ah[mi][0], ah[mi][1], ah[mi][2], ah[mi][3], bh2[0], bh2[1]);
                mma16816(c[mi][3], ah[mi][0], ah[mi][1], ah[mi][2], ah[mi][3], bh2[2], bh2[3]);
                mma16816(c[mi][0], ah[mi][0], ah[mi][1], ah[mi][2], ah[mi][3], bl[0], bl[1]);
                mma16816(c[mi][1], ah[mi][0], ah[mi][1], ah[mi][2], ah[mi][3], bl[2], bl[3]);
                mma16816(c[mi][2], ah[mi][0], ah[mi][1], ah[mi][2], ah[mi][3], bl2[0], bl2[1]);
                mma16816(c[mi][3], ah[mi][0], ah[mi][1], ah[mi][2], ah[mi][3], bl2[2], bl2[3]);
                mma16816(c[mi][0], al[mi][0], al[mi][1], al[mi][2], al[mi][3], bh[0], bh[1]);
                mma16816(c[mi][1], al[mi][0], al[mi][1], al[mi][2], al[mi][3], bh[2], bh[3]);
                mma16816(c[mi][2], al[mi][0], al[mi][1], al[mi][2], al[mi][3], bh2[0], bh2[1]);
                mma16816(c[mi][3], al[mi][0], al[mi][1], al[mi][2], al[mi][3], bh2[2], bh2[3]);
            }
        }

        // ---- epilogue ----
        const int colBase = cc * 64;
#pragma unroll
        for (int mi = 0; mi < 2; ++mi) {
#pragma unroll
            for (int ni = 0; ni < 4; ++ni) {
                int row0 = rowBase + warpM * 32 + mi * 16 + g;
                int col = colBase + warpN * 32 + ni * 8 + tig * 2;
                float b0 = bias[col], b1 = bias[col + 1];
#pragma unroll
                for (int rr = 0; rr < 2; ++rr) {
                    int row = row0 + rr * 8;
                    float2 val = make_float2(c[mi][ni][rr * 2] + b0, c[mi][ni][rr * 2 + 1] + b1);
                    if (MODE == 0) {
                        int b = row >> 6, n = row & 63;
                        int which = col / DIM;
                        int rem = col - which * DIM;
                        int h = rem >> 5, d = rem & 31;
                        size_t idx = ((((size_t)b * 3 + which) * HEADS + h) * NTOK + n) * HD + d;
                        *(float2*)(g_qkv + idx) = val;
                    } else {
                        *(float2*)(out + (size_t)row * DIM + col) = val;
                    }
                }
            }
        }
        __syncthreads();   // buffer `cur` free for prefetch next iteration
    }
}

// ---------------------------------------------------------------------------
// CPB MLP + bias gather + bias/mask combine
// ---------------------------------------------------------------------------
__global__ void cpb_table_kernel(const float* __restrict__ rpb,
                                 const float* __restrict__ w1,
                                 const float* __restrict__ b1,
                                 const float* __restrict__ w2)
{
    __shared__ float red[4][HEADS];
    const int p = blockIdx.x;
    const int tid = threadIdx.x;
    float r0 = rpb[p * 3 + 0], r1 = rpb[p * 3 + 1], r2 = rpb[p * 3 + 2];
    float acc[HEADS] = {};
    for (int j = tid; j < CPBH; j += 128) {
        float hv = fmaf(w1[j * 3 + 0], r0, fmaf(w1[j * 3 + 1], r1, fmaf(w1[j * 3 + 2], r2, b1[j])));
        hv = fmaxf(hv, 0.f);
#pragma unroll
        for (int h = 0; h < HEADS; ++h) acc[h] = fmaf(hv, w2[h * CPBH + j], acc[h]);
    }
#pragma unroll
    for (int h = 0; h < HEADS; ++h)
#pragma unroll
        for (int s = 16; s; s >>= 1) acc[h] += __shfl_xor_sync(~0u, acc[h], s);
    if ((tid & 31) == 0) {
#pragma unroll
        for (int h = 0; h < HEADS; ++h) red[tid >> 5][h] = acc[h];
    }
    __syncthreads();
    if (tid < HEADS)
        g_table[p * HEADS + tid] = red[0][tid] + red[1][tid] + red[2][tid] + red[3][tid];
}

__global__ void bias_gather_kernel(const int* __restrict__ rpb_idx)
{
    int idx = blockIdx.x * blockDim.x + threadIdx.x;
    if (idx >= HEADS * NTOK * NTOK) return;
    int h = idx / (NTOK * NTOK);
    int ij = idx % (NTOK * NTOK);
    float t = g_table[rpb_idx[ij] * HEADS + h];
    g_bias[idx] = 16.f / (1.f + expf(-t));
}

__global__ void bm_kernel(const float* __restrict__ mask)
{
    int w = blockIdx.x, h = blockIdx.y;
    const float* mp = mask + (size_t)w * NTOK * NTOK;
    const float* bp = g_bias + (size_t)h * NTOK * NTOK;
    float* o = g_bm + ((size_t)(w * HEADS + h)) * NTOK * NTOK;
    for (int ij = threadIdx.x; ij < NTOK * NTOK; ij += 256)
        o[ij] = bp[ij] + mp[ij];
}

// ---------------------------------------------------------------------------
// tensor-core attention; output written pre-split (bf16 hi/lo) for proj
// ---------------------------------------------------------------------------
#define QP  80
#define VTP 144

__global__ void __launch_bounds__(128)
attn_mma_kernel(const float* __restrict__ logit_scale)
{
    __shared__ __align__(16) char s_qhi[64 * QP], s_qlo[64 * QP];
    __shared__ __align__(16) char s_khi[64 * QP], s_klo[64 * QP];
    __shared__ __align__(16) char s_vhi[32 * VTP], s_vlo[32 * VTP];

    const int b = blockIdx.x;
    const int h = blockIdx.y;
    const int tid = threadIdx.x;

    const float scale = __expf(fminf(logit_scale[h], 4.60517018599f));

    const float* qp = g_qkv + ((((size_t)b * 3 + 0) * HEADS + h) * NTOK) * HD;
    const float* kp = g_qkv + ((((size_t)b * 3 + 1) * HEADS + h) * NTOK) * HD;
    const float* vp = g_qkv + ((((size_t)b * 3 + 2) * HEADS + h) * NTOK) * HD;

    {
        const int row = tid >> 1;
        const int half = (tid & 1) * 16;

        float qv[16];
        {
            float4 f0 = *(const float4*)(qp + row * HD + half);
            float4 f1 = *(const float4*)(qp + row * HD + half + 4);
            float4 f2 = *(const float4*)(qp + row * HD + half + 8);
            float4 f3 = *(const float4*)(qp + row * HD + half + 12);
            qv[0]=f0.x; qv[1]=f0.y; qv[2]=f0.z; qv[3]=f0.w;
            qv[4]=f1.x; qv[5]=f1.y; qv[6]=f1.z; qv[7]=f1.w;
            qv[8]=f2.x; qv[9]=f2.y; qv[10]=f2.z; qv[11]=f2.w;
            qv[12]=f3.x; qv[13]=f3.y; qv[14]=f3.z; qv[15]=f3.w;
            float ps = 0.f;
#pragma unroll
            for (int i = 0; i < 16; ++i) ps = fmaf(qv[i], qv[i], ps);
            float tot = ps + __shfl_xor_sync(~0u, ps, 1);
            float s = scale / fmaxf(sqrtf(tot), 1e-12f);
            __align__(16) __nv_bfloat16 h16[16], l16[16];
#pragma unroll
            for (int i = 0; i < 16; ++i) {
                float v = qv[i] * s;
                __nv_bfloat16 hh = __float2bfloat16(v);
                h16[i] = hh;
                l16[i] = __float2bfloat16(v - __bfloat162float(hh));
            }
            *(uint4*)(s_qhi + row * QP + half * 2)      = *(uint4*)h16;
            *(uint4*)(s_qhi + row * QP + half * 2 + 16) = *(uint4*)(h16 + 8);
            *(uint4*)(s_qlo + row * QP + half * 2)      = *(uint4*)l16;
            *(uint4*)(s_qlo + row * QP + half * 2 + 16) = *(uint4*)(l16 + 8);
        }
        {
            float4 f0 = *(const float4*)(kp + row * HD + half);
            float4 f1 = *(const float4*)(kp + row * HD + half + 4);
            float4 f2 = *(const float4*)(kp + row * HD + half + 8);
            float4 f3 = *(const float4*)(kp + row * HD + half + 12);
            float kv[16] = {f0.x,f0.y,f0.z,f0.w, f1.x,f1.y,f1.z,f1.w,
                            f2.x,f2.y,f2.z,f2.w, f3.x,f3.y,f3.z,f3.w};
            float ps = 0.f;
#pragma unroll
            for (int i = 0; i < 16; ++i) ps = fmaf(kv[i], kv[i], ps);
            float tot = ps + __shfl_xor_sync(~0u, ps, 1);
            float s = 1.f / fmaxf(sqrtf(tot), 1e-12f);
            __align__(16) __nv_bfloat16 h16[16], l16[16];
#pragma unroll
            for (int i = 0; i < 16; ++i) {
                float v = kv[i] * s;
                __nv_bfloat16 hh = __float2bfloat16(v);
                h16[i] = hh;
                l16[i] = __float2bfloat16(v - __bfloat162float(hh));
            }
            *(uint4*)(s_khi + row * QP + half * 2)      = *(uint4*)h16;
            *(uint4*)(s_khi + row * QP + half * 2 + 16) = *(uint4*)(h16 + 8);
            *(uint4*)(s_klo + row * QP + half * 2)      = *(uint4*)l16;
            *(uint4*)(s_klo + row * QP + half * 2 + 16) = *(uint4*)(l16 + 8);
        }
        {
            float4 f0 = *(const float4*)(vp + row * HD + half);
            float4 f1 = *(const float4*)(vp + row * HD + half + 4);
            float4 f2 = *(const float4*)(vp + row * HD + half + 8);
            float4 f3 = *(const float4*)(vp + row * HD + half + 12);
            float vv[16] = {f0.x,f0.y,f0.z,f0.w, f1.x,f1.y,f1.z,f1.w,
                            f2.x,f2.y,f2.z,f2.w, f3.x,f3.y,f3.z,f3.w};
#pragma unroll
            for (int i = 0; i < 16; ++i) {
                int d = half + i;
                __nv_bfloat16 hh = __float2bfloat16(vv[i]);
                *(__nv_bfloat16*)(s_vhi + d * VTP + row * 2) = hh;
                *(__nv_bfloat16*)(s_vlo + d * VTP + row * 2) =
                    __float2bfloat16(vv[i] - __bfloat162float(hh));
            }
        }
    }
    __syncthreads();

    const int w = tid >> 5;
    const int lane = tid & 31;
    const int lrow = lane & 7;
    const int lmat = lane >> 3;
    const int g = lane >> 2;
    const int tig = lane & 3;

    const uint32_t aOff = (uint32_t)((w * 16 + lrow + (lmat & 1) * 8) * QP + (lmat >> 1) * 16);
    const uint32_t bOff = (uint32_t)((lrow + (lmat >> 1) * 8) * QP + (lmat & 1) * 16);
    const uint32_t qB[3] = { smem_u32(s_qhi), smem_u32(s_qhi), smem_u32(s_qlo) };
    const uint32_t kB[3] = { smem_u32(s_khi), smem_u32(s_klo), smem_u32(s_khi) };

    float c[8][4] = {};
#pragma unroll
    for (int p = 0; p < 3; ++p) {
#pragma unroll
        for (int kt = 0; kt < 2; ++kt) {
            uint32_t a[4];
            ldsm_x4(qB[p] + aOff + kt * 32, a[0], a[1], a[2], a[3]);
#pragma unroll
            for (int nt = 0; nt < 4; ++nt) {
                uint32_t bb[4];
                ldsm_x4(kB[p] + bOff + nt * 16 * QP + kt * 32, bb[0], bb[1], bb[2], bb[3]);
                mma16816(c[nt * 2],     a[0], a[1], a[2], a[3], bb[0], bb[1]);
                mma16816(c[nt * 2 + 1], a[0], a[1], a[2], a[3], bb[2], bb[3]);
            }
        }
    }

    const float* bmp = g_bm + ((size_t)((b & (NW - 1)) * HEADS + h)) * NTOK * NTOK;
    const int r0 = w * 16 + g;
#pragma unroll
    for (int ni = 0; ni < 8; ++ni) {
        int col = ni * 8 + tig * 2;
        float2 b0 = *(const float2*)(bmp + r0 * NTOK + col);
        float2 b1 = *(const float2*)(bmp + (r0 + 8) * NTOK + col);
        c[ni][0] += b0.x; c[ni][1] += b0.y;
        c[ni][2] += b1.x; c[ni][3] += b1.y;
    }
    float mx0 = -3.4e38f, mx1 = -3.4e38f;
#pragma unroll
    for (int ni = 0; ni < 8; ++ni) {
        mx0 = fmaxf(mx0, fmaxf(c[ni][0], c[ni][1]));
        mx1 = fmaxf(mx1, fmaxf(c[ni][2], c[ni][3]));
    }
    mx0 = fmaxf(mx0, __shfl_xor_sync(~0u, mx0, 1));
    mx0 = fmaxf(mx0, __shfl_xor_sync(~0u, mx0, 2));
    mx1 = fmaxf(mx1, __shfl_xor_sync(~0u, mx1, 1));
    mx1 = fmaxf(mx1, __shfl_xor_sync(~0u, mx1, 2));
    float s0 = 0.f, s1 = 0.f;
#pragma unroll
    for (int ni = 0; ni < 8; ++ni) {
        c[ni][0] = __expf(c[ni][0] - mx0); s0 += c[ni][0];
        c[ni][1] = __expf(c[ni][1] - mx0); s0 += c[ni][1];
        c[ni][2] = __expf(c[ni][2] - mx1); s1 += c[ni][2];
        c[ni][3] = __expf(c[ni][3] - mx1); s1 += c[ni][3];
    }
    s0 += __shfl_xor_sync(~0u, s0, 1); s0 += __shfl_xor_sync(~0u, s0, 2);
    s1 += __shfl_xor_sync(~0u, s1, 1); s1 += __shfl_xor_sync(~0u, s1, 2);
    const float i0 = 1.f / s0, i1 = 1.f / s1;
#pragma unroll
    for (int ni = 0; ni < 8; ++ni) {
        c[ni][0] *= i0; c[ni][1] *= i0;
        c[ni][2] *= i1; c[ni][3] *= i1;
    }

    uint32_t aH[4][4], aL[4][4];
#pragma unroll
    for (int kt = 0; kt < 4; ++kt) {
        const float* p0 = c[2 * kt];
        const float* p1 = c[2 * kt + 1];
        float v[8] = { p0[0], p0[1], p0[2], p0[3], p1[0], p1[1], p1[2], p1[3] };
        float lo[8];
#pragma unroll
        for (int i = 0; i < 8; ++i) {
            float hf = __bfloat162float(__float2bfloat16(v[i]));
            lo[i] = v[i] - hf;
        }
        aH[kt][0] = pk_bf16(v[0], v[1]); aH[kt][1] = pk_bf16(v[2], v[3]);
        aH[kt][2] = pk_bf16(v[4], v[5]); aH[kt][3] = pk_bf16(v[6], v[7]);
        aL[kt][0] = pk_bf16(lo[0], lo[1]); aL[kt][1] = pk_bf16(lo[2], lo[3]);
        aL[kt][2] = pk_bf16(lo[4], lo[5]); aL[kt][3] = pk_bf16(lo[6], lo[7]);
    }

    const uint32_t vOff = (uint32_t)((lrow + (lmat >> 1) * 8) * VTP + (lmat & 1) * 16);
    const uint32_t vB[3] = { smem_u32(s_vhi), smem_u32(s_vlo), smem_u32(s_vhi) };

    float o[4][4] = {};
#pragma unroll
    for (int p = 0; p < 3; ++p) {
        uint32_t (*aSel)[4] = (p == 2) ? aL : aH;
#pragma unroll
        for (int kt = 0; kt < 4; ++kt) {
            uint32_t b0[4], b1[4];
            ldsm_x4(vB[p] + vOff + kt * 32,            b0[0], b0[1], b0[2], b0[3]);
            ldsm_x4(vB[p] + vOff + 16 * VTP + kt * 32, b1[0], b1[1], b1[2], b1[3]);
            mma16816(o[0], aSel[kt][0], aSel[kt][1], aSel[kt][2], aSel[kt][3], b0[0], b0[1]);
            mma16816(o[1], aSel[kt][0], aSel[kt][1], aSel[kt][2], aSel[kt][3], b0[2], b0[3]);
            mma16816(o[2], aSel[kt][0], aSel[kt][1], aSel[kt][2], aSel[kt][3], b1[0], b1[1]);
            mma16816(o[3], aSel[kt][0], aSel[kt][1], aSel[kt][2], aSel[kt][3], b1[2], b1[3]);
        }
    }

    // ---- store pre-split hi/lo to g_ahi/g_alo (heads-major concat) ----
    size_t base0 = ((size_t)b * NTOK + r0) * DIM + h * HD;
    size_t base1 = base0 + (size_t)8 * DIM;
#pragma unroll
    for (int ni = 0; ni < 4; ++ni) {
        int col = ni * 8 + tig * 2;
        float v0 = o[ni][0], v1 = o[ni][1], v2 = o[ni][2], v3 = o[ni][3];
        float h0 = __bfloat162float(__float2bfloat16(v0));
        float h1 = __bfloat162float(__float2bfloat16(v1));
        float h2 = __bfloat162float(__float2bfloat16(v2));
        float h3 = __bfloat162float(__float2bfloat16(v3));
        *(uint32_t*)(g_ahi + base0 + col) = pk_bf16(v0, v1);
        *(uint32_t*)(g_alo + base0 + col) = pk_bf16(v0 - h0, v1 - h1);
        *(uint32_t*)(g_ahi + base1 + col) = pk_bf16(v2, v3);
        *(uint32_t*)(g_alo + base1 + col) = pk_bf16(v2 - h2, v3 - h3);
    }
}

// ---------------------------------------------------------------------------
// Launch
// ---------------------------------------------------------------------------
extern "C" void kernel_launch(void* const* d_in, const int* in_sizes, int n_in,
                              void* d_out, int out_size)
{
    const float* x       = (const float*)d_in[0];
    const float* mask    = (const float*)d_in[1];
    const float* rpb     = (const float*)d_in[2];
    const int*   rpb_idx = (const int*)  d_in[3];
    const float* cpb_w1  = (const float*)d_in[4];
    const float* cpb_b1  = (const float*)d_in[5];
    const float* cpb_w2  = (const float*)d_in[6];
    const float* qkv_w   = (const float*)d_in[7];
    const float* qkv_b   = (const float*)d_in[8];
    const float* proj_w  = (const float*)d_in[9];
    const float* proj_b  = (const float*)d_in[10];
    const float* lscale  = (const float*)d_in[11];
    float* out = (float*)d_out;

    cudaFuncSetAttribute(gemm_mma_kernel<0>, cudaFuncAttributeMaxDynamicSharedMemorySize, SM_GEMM_BYTES);
    cudaFuncSetAttribute(gemm_mma_kernel<1>, cudaFuncAttributeMaxDynamicSharedMemorySize, SM_GEMM_BYTES);

    conv_w_kernel<0><<<(QKVC * DIM / 8 + 255) / 256, 256>>>(qkv_w, QKVC * DIM);
    conv_w_kernel<1><<<(DIM * DIM / 8 + 255) / 256, 256>>>(proj_w, DIM * DIM);

    cpb_table_kernel<<<NPOS, 128>>>(rpb, cpb_w1, cpb_b1, cpb_w2);
    bias_gather_kernel<<<(HEADS * NTOK * NTOK + 255) / 256, 256>>>(rpb_idx);
    bm_kernel<<<dim3(NW, HEADS), 256>>>(mask);

    gemm_mma_kernel<0><<<MROWS / 128, 256, SM_GEMM_BYTES>>>(x, qkv_b, nullptr);

    dim3 ga(BATCH, HEADS);
    attn_mma_kernel<<<ga, 128>>>(lscale);

    gemm_mma_kernel<1><<<MROWS / 128, 256, SM_GEMM_BYTES>>>(nullptr, proj_b, out);
}

// round 12
// speedup vs baseline: 1.0726x; 1.0531x over previous
#include <cuda_runtime.h>
#include <cuda_fp16.h>
#include <math.h>
#include <cstdint>

// ---------------------------------------------------------------------------
// Shapes
// ---------------------------------------------------------------------------
#define BATCH   2048
#define NTOK    64
#define DIM     192
#define HEADS   6
#define HD      32
#define QKVC    576
#define NPOS    343
#define CPBH    512
#define NW      64
#define MROWS   (BATCH * NTOK)      // 131072

// ---------------------------------------------------------------------------
// Scratch (device-code-only references!)
// ---------------------------------------------------------------------------
__device__ float g_qkv[(size_t)BATCH * 3 * HEADS * NTOK * HD];
__device__ __align__(16) __half g_ahi[(size_t)MROWS * DIM];  // attn out hi (fp16)
__device__ __align__(16) __half g_alo[(size_t)MROWS * DIM];  // attn out lo (fp16)
__device__ __align__(16) __half g_wqh[QKVC * DIM];
__device__ __align__(16) __half g_wql[QKVC * DIM];
__device__ __align__(16) __half g_wph[DIM * DIM];
__device__ __align__(16) __half g_wpl[DIM * DIM];
__device__ float g_table[NPOS * HEADS];
__device__ float g_bias[HEADS * NTOK * NTOK];
__device__ float g_bm[(size_t)NW * HEADS * NTOK * NTOK];

// ---------------------------------------------------------------------------
// helpers
// ---------------------------------------------------------------------------
__device__ __forceinline__ uint32_t smem_u32(const void* p) {
    uint32_t a;
    asm("{ .reg .u64 t; cvta.to.shared.u64 t, %1; cvt.u32.u64 %0, t; }" : "=r"(a) : "l"(p));
    return a;
}
__device__ __forceinline__ void ldsm_x4(uint32_t addr, uint32_t& r0, uint32_t& r1,
                                        uint32_t& r2, uint32_t& r3) {
    asm volatile("ldmatrix.sync.aligned.m8n8.x4.shared.b16 {%0,%1,%2,%3}, [%4];"
                 : "=r"(r0), "=r"(r1), "=r"(r2), "=r"(r3) : "r"(addr));
}
__device__ __forceinline__ void mma16816(float* c, uint32_t a0, uint32_t a1,
                                         uint32_t a2, uint32_t a3,
                                         uint32_t b0, uint32_t b1) {
    asm volatile("mma.sync.aligned.m16n8k16.row.col.f32.f16.f16.f32 "
                 "{%0,%1,%2,%3}, {%4,%5,%6,%7}, {%8,%9}, {%0,%1,%2,%3};"
                 : "+f"(c[0]), "+f"(c[1]), "+f"(c[2]), "+f"(c[3])
                 : "r"(a0), "r"(a1), "r"(a2), "r"(a3), "r"(b0), "r"(b1));
}
__device__ __forceinline__ uint32_t pk_f16(float x0, float x1) {
    __half2 t = __floats2half2_rn(x0, x1);
    return *(uint32_t*)&t;
}
__device__ __forceinline__ void cp_async16(uint32_t dst, const void* src) {
    asm volatile("cp.async.ca.shared.global [%0], [%1], 16;"
                 :: "r"(dst), "l"(src) : "memory");
}
__device__ __forceinline__ void cp_commit() {
    asm volatile("cp.async.commit_group;" ::: "memory");
}
template <int N>
__device__ __forceinline__ void cp_wait() {
    asm volatile("cp.async.wait_group %0;" :: "n"(N) : "memory");
}

// ---------------------------------------------------------------------------
// weight split-conversion (fp16 hi/lo): WHICH 0 = qkv_w, 1 = proj_w
// ---------------------------------------------------------------------------
template <int WHICH>
__global__ void conv_w_kernel(const float* __restrict__ src, int nElem)
{
    __half* hi = (WHICH == 0) ? g_wqh : g_wph;
    __half* lo = (WHICH == 0) ? g_wql : g_wpl;
    int base = (blockIdx.x * blockDim.x + threadIdx.x) * 8;
    if (base >= nElem) return;
    float4 v0 = *(const float4*)(src + base);
    float4 v1 = *(const float4*)(src + base + 4);
    float v[8] = {v0.x, v0.y, v0.z, v0.w, v1.x, v1.y, v1.z, v1.w};
    __align__(16) __half h8[8], l8[8];
#pragma unroll
    for (int i = 0; i < 8; ++i) {
        __half h = __float2half_rn(v[i]);
        h8[i] = h;
        l8[i] = __float2half_rn(v[i] - __half2float(h));
    }
    *(uint4*)(hi + base) = *(uint4*)h8;
    *(uint4*)(lo + base) = *(uint4*)l8;
}

// ---------------------------------------------------------------------------
// GEMM: 128-row CTA, 8 warps (4Mx2N), A-resident, cp.async double-buffered B,
// fragment-reuse fp16 split mma.
// MODE 0 (QKV): chunks 0-5 (q,k) 3-pass; chunks 6-8 (v) 2-pass.
// MODE 1 (proj): all chunks 2-pass; A = g_ahi/g_alo pre-split via cp.async.
// 2-pass = Ahi*Whi + Alo*Whi  (error = A*(W - fp16(W)) ~ 2^-11).
// ---------------------------------------------------------------------------
#define PITCHB 400
#define SM_AHI 0
#define SM_ALO (128 * PITCHB)                 // 51200
#define SM_B   (2 * 128 * PITCHB)             // 102400
#define SM_BUFSZ (2 * 64 * PITCHB)            // 51200 (hi+lo)
#define SM_BLO_OFF (64 * PITCHB)              // 25600
#define SM_GEMM_BYTES (SM_B + 2 * SM_BUFSZ)   // 204800

template <int MODE>
__global__ void __launch_bounds__(256, 1)
gemm_mma_kernel(const float* __restrict__ Ain,
                const float* __restrict__ bias, float* __restrict__ out)
{
    constexpr int NC = (MODE == 0) ? 9 : 3;
    const __half* __restrict__ Whi = (MODE == 0) ? g_wqh : g_wph;
    const __half* __restrict__ Wlo = (MODE == 0) ? g_wql : g_wpl;

    extern __shared__ __align__(16) char sm[];
    const int tid = threadIdx.x;
    const int wid = tid >> 5;
    const int lane = tid & 31;
    const int rowBase = blockIdx.x * 128;
    const uint32_t smBase = smem_u32(sm);

    // ---- prefetch B chunk 0 via cp.async ----
    {
        const bool fullNext = (MODE == 0);   // chunk 0 is 3-pass only for QKV
        const uint32_t dBase = smBase + SM_B;
#pragma unroll
        for (int i = tid; i < 64 * 24; i += 256) {
            int r = i / 24, c = i % 24;
            size_t gg = (size_t)r * DIM + c * 8;
            uint32_t d = dBase + r * PITCHB + c * 16;
            cp_async16(d, Whi + gg);
            if (fullNext) cp_async16(d + SM_BLO_OFF, Wlo + gg);
        }
        cp_commit();
    }

    // ---- load A ----
    if (MODE == 0) {
        // fp32 -> split to smem fp16 hi/lo
#pragma unroll
        for (int i = tid; i < 128 * 48; i += 256) {
            int r = i / 48, c4 = i % 48;
            float4 v = *(const float4*)(Ain + (size_t)(rowBase + r) * DIM + c4 * 4);
            float vv[4] = {v.x, v.y, v.z, v.w};
            __align__(8) __half h4[4], l4[4];
#pragma unroll
            for (int q = 0; q < 4; ++q) {
                __half h = __float2half_rn(vv[q]);
                h4[q] = h;
                l4[q] = __float2half_rn(vv[q] - __half2float(h));
            }
            *(uint2*)(sm + SM_AHI + r * PITCHB + c4 * 8) = *(uint2*)h4;
            *(uint2*)(sm + SM_ALO + r * PITCHB + c4 * 8) = *(uint2*)l4;
        }
    } else {
        // pre-split fp16 hi/lo via cp.async
#pragma unroll
        for (int i = tid; i < 128 * 24; i += 256) {
            int r = i / 24, c = i % 24;
            size_t gg = (size_t)(rowBase + r) * DIM + c * 8;
            cp_async16(smBase + SM_AHI + r * PITCHB + c * 16, g_ahi + gg);
            cp_async16(smBase + SM_ALO + r * PITCHB + c * 16, g_alo + gg);
        }
        cp_commit();
    }

    const int warpM = wid >> 1;
    const int warpN = wid & 1;
    const int lrow = lane & 7;
    const int lmat = lane >> 3;

    const uint32_t aOff = (uint32_t)((warpM * 32 + lrow + (lmat & 1) * 8) * PITCHB
                                     + (lmat >> 1) * 16);
    const uint32_t bOff = (uint32_t)((warpN * 32 + lrow + (lmat >> 1) * 8) * PITCHB
                                     + (lmat & 1) * 16);
    const uint32_t aHiB = smBase + SM_AHI + aOff;
    const uint32_t aLoB = smBase + SM_ALO + aOff;
    const int g = lane >> 2, tig = lane & 3;

    for (int cc = 0; cc < NC; ++cc) {
        const int cur = cc & 1;
        const bool full = (MODE == 0) && (cc < 6);   // 3-pass for q/k chunks
        // prefetch next chunk into the other buffer, then wait for current
        if (cc + 1 < NC) {
            const bool fullNext = (MODE == 0) && (cc + 1 < 6);
            const uint32_t dBase = smBase + SM_B + (1 - cur) * SM_BUFSZ;
            const int colN = (cc + 1) * 64;
#pragma unroll
            for (int i = tid; i < 64 * 24; i += 256) {
                int r = i / 24, c = i % 24;
                size_t gg = (size_t)(colN + r) * DIM + c * 8;
                uint32_t d = dBase + r * PITCHB + c * 16;
                cp_async16(d, Whi + gg);
                if (fullNext) cp_async16(d + SM_BLO_OFF, Wlo + gg);
            }
            cp_commit();
            cp_wait<1>();
        } else {
            cp_wait<0>();
        }
        __syncthreads();

        const uint32_t bHiT = smBase + SM_B + cur * SM_BUFSZ + bOff;
        const uint32_t bLoT = bHiT + SM_BLO_OFF;

        float c[2][4][4] = {};
#pragma unroll
        for (int k = 0; k < 12; ++k) {
            uint32_t ah[2][4], al[2][4];
            uint32_t bh[4], bh2[4], bl[4], bl2[4];
            ldsm_x4(aHiB + k * 32,               ah[0][0], ah[0][1], ah[0][2], ah[0][3]);
            ldsm_x4(aHiB + 16 * PITCHB + k * 32, ah[1][0], ah[1][1], ah[1][2], ah[1][3]);
            ldsm_x4(aLoB + k * 32,               al[0][0], al[0][1], al[0][2], al[0][3]);
            ldsm_x4(aLoB + 16 * PITCHB + k * 32, al[1][0], al[1][1], al[1][2], al[1][3]);
            ldsm_x4(bHiT + k * 32,               bh[0], bh[1], bh[2], bh[3]);
            ldsm_x4(bHiT + 16 * PITCHB + k * 32, bh2[0], bh2[1], bh2[2], bh2[3]);
            if (full) {
                ldsm_x4(bLoT + k * 32,               bl[0], bl[1], bl[2], bl[3]);
                ldsm_x4(bLoT + 16 * PITCHB + k * 32, bl2[0], bl2[1], bl2[2], bl2[3]);
            }
#pragma unroll
            for (int mi = 0; mi < 2; ++mi) {
                // pass 0: Ahi x Whi
                mma16816(c[mi][0], ah[mi][0], ah[mi][1], ah[mi][2], ah[mi][3], bh[0], bh[1]);
                mma16816(c[mi][1], ah[mi][0], ah[mi][1], ah[mi][2], ah[mi][3], bh[2], bh[3]);
                mma16816(c[mi][2], ah[mi][0], ah[mi][1], ah[mi][2], ah[mi][3], bh2[0], bh2[1]);
                mma16816(c[mi][3], ah[mi][0], ah[mi][1], ah[mi][2], ah[mi][3], bh2[2], bh2[3]);
                // pass 1: Ahi x Wlo (3-pass chunks only)
                if (full) {
                    mma16816(c[mi][0], ah[mi][0], ah[mi][1], ah[mi][2], ah[mi][3], bl[0], bl[1]);
                    mma16816(c[mi][1], ah[mi][0], ah[mi][1], ah[mi][2], ah[mi][3], bl[2], bl[3]);
                    mma16816(c[mi][2], ah[mi][0], ah[mi][1], ah[mi][2], ah[mi][3], bl2[0], bl2[1]);
                    mma16816(c[mi][3], ah[mi][0], ah[mi][1], ah[mi][2], ah[mi][3], bl2[2], bl2[3]);
                }
                // pass 2: Alo x Whi
                mma16816(c[mi][0], al[mi][0], al[mi][1], al[mi][2], al[mi][3], bh[0], bh[1]);
                mma16816(c[mi][1], al[mi][0], al[mi][1], al[mi][2], al[mi][3], bh[2], bh[3]);
                mma16816(c[mi][2], al[mi][0], al[mi][1], al[mi][2], al[mi][3], bh2[0], bh2[1]);
                mma16816(c[mi][3], al[mi][0], al[mi][1], al[mi][2], al[mi][3], bh2[2], bh2[3]);
            }
        }

        // ---- epilogue ----
        const int colBase = cc * 64;
#pragma unroll
        for (int mi = 0; mi < 2; ++mi) {
#pragma unroll
            for (int ni = 0; ni < 4; ++ni) {
                int row0 = rowBase + warpM * 32 + mi * 16 + g;
                int col = colBase + warpN * 32 + ni * 8 + tig * 2;
                float b0 = bias[col], b1 = bias[col + 1];
#pragma unroll
                for (int rr = 0; rr < 2; ++rr) {
                    int row = row0 + rr * 8;
                    float2 val = make_float2(c[mi][ni][rr * 2] + b0, c[mi][ni][rr * 2 + 1] + b1);
                    if (MODE == 0) {
                        int b = row >> 6, n = row & 63;
                        int which = col / DIM;
                        int rem = col - which * DIM;
                        int h = rem >> 5, d = rem & 31;
                        size_t idx = ((((size_t)b * 3 + which) * HEADS + h) * NTOK + n) * HD + d;
                        *(float2*)(g_qkv + idx) = val;
                    } else {
                        *(float2*)(out + (size_t)row * DIM + col) = val;
                    }
                }
            }
        }
        __syncthreads();
    }
}

// ---------------------------------------------------------------------------
// CPB MLP + bias gather + bias/mask combine
// ---------------------------------------------------------------------------
__global__ void cpb_table_kernel(const float* __restrict__ rpb,
                                 const float* __restrict__ w1,
                                 const float* __restrict__ b1,
                                 const float* __restrict__ w2)
{
    __shared__ float red[4][HEADS];
    const int p = blockIdx.x;
    const int tid = threadIdx.x;
    float r0 = rpb[p * 3 + 0], r1 = rpb[p * 3 + 1], r2 = rpb[p * 3 + 2];
    float acc[HEADS] = {};
    for (int j = tid; j < CPBH; j += 128) {
        float hv = fmaf(w1[j * 3 + 0], r0, fmaf(w1[j * 3 + 1], r1, fmaf(w1[j * 3 + 2], r2, b1[j])));
        hv = fmaxf(hv, 0.f);
#pragma unroll
        for (int h = 0; h < HEADS; ++h) acc[h] = fmaf(hv, w2[h * CPBH + j], acc[h]);
    }
#pragma unroll
    for (int h = 0; h < HEADS; ++h)
#pragma unroll
        for (int s = 16; s; s >>= 1) acc[h] += __shfl_xor_sync(~0u, acc[h], s);
    if ((tid & 31) == 0) {
#pragma unroll
        for (int h = 0; h < HEADS; ++h) red[tid >> 5][h] = acc[h];
    }
    __syncthreads();
    if (tid < HEADS)
        g_table[p * HEADS + tid] = red[0][tid] + red[1][tid] + red[2][tid] + red[3][tid];
}

__global__ void bias_gather_kernel(const int* __restrict__ rpb_idx)
{
    int idx = blockIdx.x * blockDim.x + threadIdx.x;
    if (idx >= HEADS * NTOK * NTOK) return;
    int h = idx / (NTOK * NTOK);
    int ij = idx % (NTOK * NTOK);
    float t = g_table[rpb_idx[ij] * HEADS + h];
    g_bias[idx] = 16.f / (1.f + expf(-t));
}

__global__ void bm_kernel(const float* __restrict__ mask)
{
    int w = blockIdx.x, h = blockIdx.y;
    const float* mp = mask + (size_t)w * NTOK * NTOK;
    const float* bp = g_bias + (size_t)h * NTOK * NTOK;
    float* o = g_bm + ((size_t)(w * HEADS + h)) * NTOK * NTOK;
    for (int ij = threadIdx.x; ij < NTOK * NTOK; ij += 256)
        o[ij] = bp[ij] + mp[ij];
}

// ---------------------------------------------------------------------------
// tensor-core attention (fp16 splits, 3-pass QK + 3-pass PV);
// output written pre-split fp16 hi/lo for proj
// ---------------------------------------------------------------------------
#define QP  80
#define VTP 144

__global__ void __launch_bounds__(128)
attn_mma_kernel(const float* __restrict__ logit_scale)
{
    __shared__ __align__(16) char s_qhi[64 * QP], s_qlo[64 * QP];
    __shared__ __align__(16) char s_khi[64 * QP], s_klo[64 * QP];
    __shared__ __align__(16) char s_vhi[32 * VTP], s_vlo[32 * VTP];

    const int b = blockIdx.x;
    const int h = blockIdx.y;
    const int tid = threadIdx.x;

    const float scale = __expf(fminf(logit_scale[h], 4.60517018599f));

    const float* qp = g_qkv + ((((size_t)b * 3 + 0) * HEADS + h) * NTOK) * HD;
    const float* kp = g_qkv + ((((size_t)b * 3 + 1) * HEADS + h) * NTOK) * HD;
    const float* vp = g_qkv + ((((size_t)b * 3 + 2) * HEADS + h) * NTOK) * HD;

    {
        const int row = tid >> 1;
        const int half = (tid & 1) * 16;

        float qv[16];
        {
            float4 f0 = *(const float4*)(qp + row * HD + half);
            float4 f1 = *(const float4*)(qp + row * HD + half + 4);
            float4 f2 = *(const float4*)(qp + row * HD + half + 8);
            float4 f3 = *(const float4*)(qp + row * HD + half + 12);
            qv[0]=f0.x; qv[1]=f0.y; qv[2]=f0.z; qv[3]=f0.w;
            qv[4]=f1.x; qv[5]=f1.y; qv[6]=f1.z; qv[7]=f1.w;
            qv[8]=f2.x; qv[9]=f2.y; qv[10]=f2.z; qv[11]=f2.w;
            qv[12]=f3.x; qv[13]=f3.y; qv[14]=f3.z; qv[15]=f3.w;
            float ps = 0.f;
#pragma unroll
            for (int i = 0; i < 16; ++i) ps = fmaf(qv[i], qv[i], ps);
            float tot = ps + __shfl_xor_sync(~0u, ps, 1);
            float s = scale / fmaxf(sqrtf(tot), 1e-12f);
            __align__(16) __half h16[16], l16[16];
#pragma unroll
            for (int i = 0; i < 16; ++i) {
                float v = qv[i] * s;
                __half hh = __float2half_rn(v);
                h16[i] = hh;
                l16[i] = __float2half_rn(v - __half2float(hh));
            }
            *(uint4*)(s_qhi + row * QP + half * 2)      = *(uint4*)h16;
            *(uint4*)(s_qhi + row * QP + half * 2 + 16) = *(uint4*)(h16 + 8);
            *(uint4*)(s_qlo + row * QP + half * 2)      = *(uint4*)l16;
            *(uint4*)(s_qlo + row * QP + half * 2 + 16) = *(uint4*)(l16 + 8);
        }
        {
            float4 f0 = *(const float4*)(kp + row * HD + half);
            float4 f1 = *(const float4*)(kp + row * HD + half + 4);
            float4 f2 = *(const float4*)(kp + row * HD + half + 8);
            float4 f3 = *(const float4*)(kp + row * HD + half + 12);
            float kv[16] = {f0.x,f0.y,f0.z,f0.w, f1.x,f1.y,f1.z,f1.w,
                            f2.x,f2.y,f2.z,f2.w, f3.x,f3.y,f3.z,f3.w};
            float ps = 0.f;
#pragma unroll
            for (int i = 0; i < 16; ++i) ps = fmaf(kv[i], kv[i], ps);
            float tot = ps + __shfl_xor_sync(~0u, ps, 1);
            float s = 1.f / fmaxf(sqrtf(tot), 1e-12f);
            __align__(16) __half h16[16], l16[16];
#pragma unroll
            for (int i = 0; i < 16; ++i) {
                float v = kv[i] * s;
                __half hh = __float2half_rn(v);
                h16[i] = hh;
                l16[i] = __float2half_rn(v - __half2float(hh));
            }
            *(uint4*)(s_khi + row * QP + half * 2)      = *(uint4*)h16;
            *(uint4*)(s_khi + row * QP + half * 2 + 16) = *(uint4*)(h16 + 8);
            *(uint4*)(s_klo + row * QP + half * 2)      = *(uint4*)l16;
            *(uint4*)(s_klo + row * QP + half * 2 + 16) = *(uint4*)(l16 + 8);
        }
        {
            float4 f0 = *(const float4*)(vp + row * HD + half);
            float4 f1 = *(const float4*)(vp + row * HD + half + 4);
            float4 f2 = *(const float4*)(vp + row * HD + half + 8);
            float4 f3 = *(const float4*)(vp + row * HD + half + 12);
            float vv[16] = {f0.x,f0.y,f0.z,f0.w, f1.x,f1.y,f1.z,f1.w,
                            f2.x,f2.y,f2.z,f2.w, f3.x,f3.y,f3.z,f3.w};
#pragma unroll
            for (int i = 0; i < 16; ++i) {
                int d = half + i;
                __half hh = __float2half_rn(vv[i]);
                *(__half*)(s_vhi + d * VTP + row * 2) = hh;
                *(__half*)(s_vlo + d * VTP + row * 2) =
                    __float2half_rn(vv[i] - __half2float(hh));
            }
        }
    }
    __syncthreads();

    const int w = tid >> 5;
    const int lane = tid & 31;
    const int lrow = lane & 7;
    const int lmat = lane >> 3;
    const int g = lane >> 2;
    const int tig = lane & 3;

    const uint32_t aOff = (uint32_t)((w * 16 + lrow + (lmat & 1) * 8) * QP + (lmat >> 1) * 16);
    const uint32_t bOff = (uint32_t)((lrow + (lmat >> 1) * 8) * QP + (lmat & 1) * 16);
    const uint32_t qB[3] = { smem_u32(s_qhi), smem_u32(s_qhi), smem_u32(s_qlo) };
    const uint32_t kB[3] = { smem_u32(s_khi), smem_u32(s_klo), smem_u32(s_khi) };

    float c[8][4] = {};
#pragma unroll
    for (int p = 0; p < 3; ++p) {
#pragma unroll
        for (int kt = 0; kt < 2; ++kt) {
            uint32_t a[4];
            ldsm_x4(qB[p] + aOff + kt * 32, a[0], a[1], a[2], a[3]);
#pragma unroll
            for (int nt = 0; nt < 4; ++nt) {
                uint32_t bb[4];
                ldsm_x4(kB[p] + bOff + nt * 16 * QP + kt * 32, bb[0], bb[1], bb[2], bb[3]);
                mma16816(c[nt * 2],     a[0], a[1], a[2], a[3], bb[0], bb[1]);
                mma16816(c[nt * 2 + 1], a[0], a[1], a[2], a[3], bb[2], bb[3]);
            }
        }
    }

    const float* bmp = g_bm + ((size_t)((b & (NW - 1)) * HEADS + h)) * NTOK * NTOK;
    const int r0 = w * 16 + g;
#pragma unroll
    for (int ni = 0; ni < 8; ++ni) {
        int col = ni * 8 + tig * 2;
        float2 b0 = *(const float2*)(bmp + r0 * NTOK + col);
        float2 b1 = *(const float2*)(bmp + (r0 + 8) * NTOK + col);
        c[ni][0] += b0.x; c[ni][1] += b0.y;
        c[ni][2] += b1.x; c[ni][3] += b1.y;
    }
    float mx0 = -3.4e38f, mx1 = -3.4e38f;
#pragma unroll
    for (int ni = 0; ni < 8; ++ni) {
        mx0 = fmaxf(mx0, fmaxf(c[ni][0], c[ni][1]));
        mx1 = fmaxf(mx1, fmaxf(c[ni][2], c[ni][3]));
    }
    mx0 = fmaxf(mx0, __shfl_xor_sync(~0u, mx0, 1));
    mx0 = fmaxf(mx0, __shfl_xor_sync(~0u, mx0, 2));
    mx1 = fmaxf(mx1, __shfl_xor_sync(~0u, mx1, 1));
    mx1 = fmaxf(mx1, __shfl_xor_sync(~0u, mx1, 2));
    float s0 = 0.f, s1 = 0.f;
#pragma unroll
    for (int ni = 0; ni < 8; ++ni) {
        c[ni][0] = __expf(c[ni][0] - mx0); s0 += c[ni][0];
        c[ni][1] = __expf(c[ni][1] - mx0); s0 += c[ni][1];
        c[ni][2] = __expf(c[ni][2] - mx1); s1 += c[ni][2];
        c[ni][3] = __expf(c[ni][3] - mx1); s1 += c[ni][3];
    }
    s0 += __shfl_xor_sync(~0u, s0, 1); s0 += __shfl_xor_sync(~0u, s0, 2);
    s1 += __shfl_xor_sync(~0u, s1, 1); s1 += __shfl_xor_sync(~0u, s1, 2);
    const float i0 = 1.f / s0, i1 = 1.f / s1;
#pragma unroll
    for (int ni = 0; ni < 8; ++ni) {
        c[ni][0] *= i0; c[ni][1] *= i0;
        c[ni][2] *= i1; c[ni][3] *= i1;
    }

    uint32_t aH[4][4], aL[4][4];
#pragma unroll
    for (int kt = 0; kt < 4; ++kt) {
        const float* p0 = c[2 * kt];
        const float* p1 = c[2 * kt + 1];
        float v[8] = { p0[0], p0[1], p0[2], p0[3], p1[0], p1[1], p1[2], p1[3] };
        float lo[8];
#pragma unroll
        for (int i = 0; i < 8; ++i) {
            float hf = __half2float(__float2half_rn(v[i]));
            lo[i] = v[i] - hf;
        }
        aH[kt][0] = pk_f16(v[0], v[1]); aH[kt][1] = pk_f16(v[2], v[3]);
        aH[kt][2] = pk_f16(v[4], v[5]); aH[kt][3] = pk_f16(v[6], v[7]);
        aL[kt][0] = pk_f16(lo[0], lo[1]); aL[kt][1] = pk_f16(lo[2], lo[3]);
        aL[kt][2] = pk_f16(lo[4], lo[5]); aL[kt][3] = pk_f16(lo[6], lo[7]);
    }

    const uint32_t vOff = (uint32_t)((lrow + (lmat >> 1) * 8) * VTP + (lmat & 1) * 16);
    const uint32_t vB[3] = { smem_u32(s_vhi), smem_u32(s_vlo), smem_u32(s_vhi) };

    float o[4][4] = {};
#pragma unroll
    for (int p = 0; p < 3; ++p) {
        uint32_t (*aSel)[4] = (p == 2) ? aL : aH;
#pragma unroll
        for (int kt = 0; kt < 4; ++kt) {
            uint32_t b0[4], b1[4];
            ldsm_x4(vB[p] + vOff + kt * 32,            b0[0], b0[1], b0[2], b0[3]);
            ldsm_x4(vB[p] + vOff + 16 * VTP + kt * 32, b1[0], b1[1], b1[2], b1[3]);
            mma16816(o[0], aSel[kt][0], aSel[kt][1], aSel[kt][2], aSel[kt][3], b0[0], b0[1]);
            mma16816(o[1], aSel[kt][0], aSel[kt][1], aSel[kt][2], aSel[kt][3], b0[2], b0[3]);
            mma16816(o[2], aSel[kt][0], aSel[kt][1], aSel[kt][2], aSel[kt][3], b1[0], b1[1]);
            mma16816(o[3], aSel[kt][0], aSel[kt][1], aSel[kt][2], aSel[kt][3], b1[2], b1[3]);
        }
    }

    // ---- store pre-split fp16 hi/lo to g_ahi/g_alo (heads-major concat) ----
    size_t base0 = ((size_t)b * NTOK + r0) * DIM + h * HD;
    size_t base1 = base0 + (size_t)8 * DIM;
#pragma unroll
    for (int ni = 0; ni < 4; ++ni) {
        int col = ni * 8 + tig * 2;
        float v0 = o[ni][0], v1 = o[ni][1], v2 = o[ni][2], v3 = o[ni][3];
        float h0 = __half2float(__float2half_rn(v0));
        float h1 = __half2float(__float2half_rn(v1));
        float h2 = __half2float(__float2half_rn(v2));
        float h3 = __half2float(__float2half_rn(v3));
        *(uint32_t*)(g_ahi + base0 + col) = pk_f16(v0, v1);
        *(uint32_t*)(g_alo + base0 + col) = pk_f16(v0 - h0, v1 - h1);
        *(uint32_t*)(g_ahi + base1 + col) = pk_f16(v2, v3);
        *(uint32_t*)(g_alo + base1 + col) = pk_f16(v2 - h2, v3 - h3);
    }
}

// ---------------------------------------------------------------------------
// Launch
// ---------------------------------------------------------------------------
extern "C" void kernel_launch(void* const* d_in, const int* in_sizes, int n_in,
                              void* d_out, int out_size)
{
    const float* x       = (const float*)d_in[0];
    const float* mask    = (const float*)d_in[1];
    const float* rpb     = (const float*)d_in[2];
    const int*   rpb_idx = (const int*)  d_in[3];
    const float* cpb_w1  = (const float*)d_in[4];
    const float* cpb_b1  = (const float*)d_in[5];
    const float* cpb_w2  = (const float*)d_in[6];
    const float* qkv_w   = (const float*)d_in[7];
    const float* qkv_b   = (const float*)d_in[8];
    const float* proj_w  = (const float*)d_in[9];
    const float* proj_b  = (const float*)d_in[10];
    const float* lscale  = (const float*)d_in[11];
    float* out = (float*)d_out;

    cudaFuncSetAttribute(gemm_mma_kernel<0>, cudaFuncAttributeMaxDynamicSharedMemorySize, SM_GEMM_BYTES);
    cudaFuncSetAttribute(gemm_mma_kernel<1>, cudaFuncAttributeMaxDynamicSharedMemorySize, SM_GEMM_BYTES);

    conv_w_kernel<0><<<(QKVC * DIM / 8 + 255) / 256, 256>>>(qkv_w, QKVC * DIM);
    conv_w_kernel<1><<<(DIM * DIM / 8 + 255) / 256, 256>>>(proj_w, DIM * DIM);

    cpb_table_kernel<<<NPOS, 128>>>(rpb, cpb_w1, cpb_b1, cpb_w2);
    bias_gather_kernel<<<(HEADS * NTOK * NTOK + 255) / 256, 256>>>(rpb_idx);
    bm_kernel<<<dim3(NW, HEADS), 256>>>(mask);

    gemm_mma_kernel<0><<<MROWS / 128, 256, SM_GEMM_BYTES>>>(x, qkv_b, nullptr);

    dim3 ga(BATCH, HEADS);
    attn_mma_kernel<<<ga, 128>>>(lscale);

    gemm_mma_kernel<1><<<MROWS / 128, 256, SM_GEMM_BYTES>>>(nullptr, proj_b, out);
}

// round 13
// speedup vs baseline: 1.1099x; 1.0348x over previous
#include <cuda_runtime.h>
#include <cuda_fp16.h>
#include <math.h>
#include <cstdint>

// ---------------------------------------------------------------------------
// Shapes
// ---------------------------------------------------------------------------
#define BATCH   2048
#define NTOK    64
#define DIM     192
#define HEADS   6
#define HD      32
#define QKVC    576
#define NPOS    343
#define CPBH    512
#define NW      64
#define MROWS   (BATCH * NTOK)      // 131072

// ---------------------------------------------------------------------------
// Scratch (device-code-only references!)
// ---------------------------------------------------------------------------
__device__ float g_qkv[(size_t)BATCH * 3 * HEADS * NTOK * HD];
__device__ __align__(16) __half g_ahi[(size_t)MROWS * DIM];
__device__ __align__(16) __half g_alo[(size_t)MROWS * DIM];
__device__ __align__(16) __half g_wqh[QKVC * DIM];
__device__ __align__(16) __half g_wql[QKVC * DIM];
__device__ __align__(16) __half g_wph[DIM * DIM];
__device__ __align__(16) __half g_wpl[DIM * DIM];
__device__ float g_table[NPOS * HEADS];
__device__ float g_bm[(size_t)NW * HEADS * NTOK * NTOK];

// ---------------------------------------------------------------------------
// helpers
// ---------------------------------------------------------------------------
__device__ __forceinline__ uint32_t smem_u32(const void* p) {
    uint32_t a;
    asm("{ .reg .u64 t; cvta.to.shared.u64 t, %1; cvt.u32.u64 %0, t; }" : "=r"(a) : "l"(p));
    return a;
}
__device__ __forceinline__ void ldsm_x4(uint32_t addr, uint32_t& r0, uint32_t& r1,
                                        uint32_t& r2, uint32_t& r3) {
    asm volatile("ldmatrix.sync.aligned.m8n8.x4.shared.b16 {%0,%1,%2,%3}, [%4];"
                 : "=r"(r0), "=r"(r1), "=r"(r2), "=r"(r3) : "r"(addr));
}
__device__ __forceinline__ void mma16816(float* c, uint32_t a0, uint32_t a1,
                                         uint32_t a2, uint32_t a3,
                                         uint32_t b0, uint32_t b1) {
    asm volatile("mma.sync.aligned.m16n8k16.row.col.f32.f16.f16.f32 "
                 "{%0,%1,%2,%3}, {%4,%5,%6,%7}, {%8,%9}, {%0,%1,%2,%3};"
                 : "+f"(c[0]), "+f"(c[1]), "+f"(c[2]), "+f"(c[3])
                 : "r"(a0), "r"(a1), "r"(a2), "r"(a3), "r"(b0), "r"(b1));
}
__device__ __forceinline__ uint32_t pk_f16(float x0, float x1) {
    __half2 t = __floats2half2_rn(x0, x1);
    return *(uint32_t*)&t;
}
__device__ __forceinline__ void cp_async16(uint32_t dst, const void* src) {
    asm volatile("cp.async.ca.shared.global [%0], [%1], 16;"
                 :: "r"(dst), "l"(src) : "memory");
}
__device__ __forceinline__ void cp_commit() {
    asm volatile("cp.async.commit_group;" ::: "memory");
}
template <int N>
__device__ __forceinline__ void cp_wait() {
    asm volatile("cp.async.wait_group %0;" :: "n"(N) : "memory");
}

// ---------------------------------------------------------------------------
// merged weight split-conversion: covers qkv_w then proj_w in one launch
// ---------------------------------------------------------------------------
#define QKV_ELEMS (QKVC * DIM)      // 110592
#define PROJ_ELEMS (DIM * DIM)      // 36864
__global__ void conv_w_all_kernel(const float* __restrict__ qkv_w,
                                  const float* __restrict__ proj_w)
{
    int base = (blockIdx.x * blockDim.x + threadIdx.x) * 8;
    const float* src;
    __half *hi, *lo;
    if (base < QKV_ELEMS) {
        src = qkv_w; hi = g_wqh; lo = g_wql;
    } else {
        base -= QKV_ELEMS;
        if (base >= PROJ_ELEMS) return;
        src = proj_w; hi = g_wph; lo = g_wpl;
    }
    float4 v0 = *(const float4*)(src + base);
    float4 v1 = *(const float4*)(src + base + 4);
    float v[8] = {v0.x, v0.y, v0.z, v0.w, v1.x, v1.y, v1.z, v1.w};
    __align__(16) __half h8[8], l8[8];
#pragma unroll
    for (int i = 0; i < 8; ++i) {
        __half h = __float2half_rn(v[i]);
        h8[i] = h;
        l8[i] = __float2half_rn(v[i] - __half2float(h));
    }
    *(uint4*)(hi + base) = *(uint4*)h8;
    *(uint4*)(lo + base) = *(uint4*)l8;
}

// ---------------------------------------------------------------------------
// GEMM: 128-row CTA, 8 warps (4Mx2N), A-resident, cp.async double-buffered B,
// fragment-reuse fp16 split mma.
// MODE 0 (QKV): chunks 0-5 (q,k) 3-pass; chunks 6-8 (v) 2-pass.
// MODE 1 (proj): all chunks 2-pass; A = g_ahi/g_alo pre-split via cp.async.
// ---------------------------------------------------------------------------
#define PITCHB 400
#define SM_AHI 0
#define SM_ALO (128 * PITCHB)
#define SM_B   (2 * 128 * PITCHB)
#define SM_BUFSZ (2 * 64 * PITCHB)
#define SM_BLO_OFF (64 * PITCHB)
#define SM_GEMM_BYTES (SM_B + 2 * SM_BUFSZ)   // 204800

template <int MODE>
__global__ void __launch_bounds__(256, 1)
gemm_mma_kernel(const float* __restrict__ Ain,
                const float* __restrict__ bias, float* __restrict__ out)
{
    constexpr int NC = (MODE == 0) ? 9 : 3;
    const __half* __restrict__ Whi = (MODE == 0) ? g_wqh : g_wph;
    const __half* __restrict__ Wlo = (MODE == 0) ? g_wql : g_wpl;

    extern __shared__ __align__(16) char sm[];
    const int tid = threadIdx.x;
    const int wid = tid >> 5;
    const int lane = tid & 31;
    const int rowBase = blockIdx.x * 128;
    const uint32_t smBase = smem_u32(sm);

    // ---- prefetch B chunk 0 ----
    {
        const bool fullNext = (MODE == 0);
        const uint32_t dBase = smBase + SM_B;
#pragma unroll
        for (int i = tid; i < 64 * 24; i += 256) {
            int r = i / 24, c = i % 24;
            size_t gg = (size_t)r * DIM + c * 8;
            uint32_t d = dBase + r * PITCHB + c * 16;
            cp_async16(d, Whi + gg);
            if (fullNext) cp_async16(d + SM_BLO_OFF, Wlo + gg);
        }
        cp_commit();
    }

    // ---- load A ----
    if (MODE == 0) {
#pragma unroll
        for (int i = tid; i < 128 * 48; i += 256) {
            int r = i / 48, c4 = i % 48;
            float4 v = *(const float4*)(Ain + (size_t)(rowBase + r) * DIM + c4 * 4);
            float vv[4] = {v.x, v.y, v.z, v.w};
            __align__(8) __half h4[4], l4[4];
#pragma unroll
            for (int q = 0; q < 4; ++q) {
                __half h = __float2half_rn(vv[q]);
                h4[q] = h;
                l4[q] = __float2half_rn(vv[q] - __half2float(h));
            }
            *(uint2*)(sm + SM_AHI + r * PITCHB + c4 * 8) = *(uint2*)h4;
            *(uint2*)(sm + SM_ALO + r * PITCHB + c4 * 8) = *(uint2*)l4;
        }
    } else {
#pragma unroll
        for (int i = tid; i < 128 * 24; i += 256) {
            int r = i / 24, c = i % 24;
            size_t gg = (size_t)(rowBase + r) * DIM + c * 8;
            cp_async16(smBase + SM_AHI + r * PITCHB + c * 16, g_ahi + gg);
            cp_async16(smBase + SM_ALO + r * PITCHB + c * 16, g_alo + gg);
        }
        cp_commit();
    }

    const int warpM = wid >> 1;
    const int warpN = wid & 1;
    const int lrow = lane & 7;
    const int lmat = lane >> 3;

    const uint32_t aOff = (uint32_t)((warpM * 32 + lrow + (lmat & 1) * 8) * PITCHB
                                     + (lmat >> 1) * 16);
    const uint32_t bOff = (uint32_t)((warpN * 32 + lrow + (lmat >> 1) * 8) * PITCHB
                                     + (lmat & 1) * 16);
    const uint32_t aHiB = smBase + SM_AHI + aOff;
    const uint32_t aLoB = smBase + SM_ALO + aOff;
    const int g = lane >> 2, tig = lane & 3;

    for (int cc = 0; cc < NC; ++cc) {
        const int cur = cc & 1;
        const bool full = (MODE == 0) && (cc < 6);
        if (cc + 1 < NC) {
            const bool fullNext = (MODE == 0) && (cc + 1 < 6);
            const uint32_t dBase = smBase + SM_B + (1 - cur) * SM_BUFSZ;
            const int colN = (cc + 1) * 64;
#pragma unroll
            for (int i = tid; i < 64 * 24; i += 256) {
                int r = i / 24, c = i % 24;
                size_t gg = (size_t)(colN + r) * DIM + c * 8;
                uint32_t d = dBase + r * PITCHB + c * 16;
                cp_async16(d, Whi + gg);
                if (fullNext) cp_async16(d + SM_BLO_OFF, Wlo + gg);
            }
            cp_commit();
            cp_wait<1>();
        } else {
            cp_wait<0>();
        }
        __syncthreads();

        const uint32_t bHiT = smBase + SM_B + cur * SM_BUFSZ + bOff;
        const uint32_t bLoT = bHiT + SM_BLO_OFF;

        float c[2][4][4] = {};
#pragma unroll
        for (int k = 0; k < 12; ++k) {
            uint32_t ah[2][4], al[2][4];
            uint32_t bh[4], bh2[4], bl[4], bl2[4];
            ldsm_x4(aHiB + k * 32,               ah[0][0], ah[0][1], ah[0][2], ah[0][3]);
            ldsm_x4(aHiB + 16 * PITCHB + k * 32, ah[1][0], ah[1][1], ah[1][2], ah[1][3]);
            ldsm_x4(aLoB + k * 32,               al[0][0], al[0][1], al[0][2], al[0][3]);
            ldsm_x4(aLoB + 16 * PITCHB + k * 32, al[1][0], al[1][1], al[1][2], al[1][3]);
            ldsm_x4(bHiT + k * 32,               bh[0], bh[1], bh[2], bh[3]);
            ldsm_x4(bHiT + 16 * PITCHB + k * 32, bh2[0], bh2[1], bh2[2], bh2[3]);
            if (full) {
                ldsm_x4(bLoT + k * 32,               bl[0], bl[1], bl[2], bl[3]);
                ldsm_x4(bLoT + 16 * PITCHB + k * 32, bl2[0], bl2[1], bl2[2], bl2[3]);
            }
#pragma unroll
            for (int mi = 0; mi < 2; ++mi) {
                mma16816(c[mi][0], ah[mi][0], ah[mi][1], ah[mi][2], ah[mi][3], bh[0], bh[1]);
                mma16816(c[mi][1], ah[mi][0], ah[mi][1], ah[mi][2], ah[mi][3], bh[2], bh[3]);
                mma16816(c[mi][2], ah[mi][0], ah[mi][1], ah[mi][2], ah[mi][3], bh2[0], bh2[1]);
                mma16816(c[mi][3], ah[mi][0], ah[mi][1], ah[mi][2], ah[mi][3], bh2[2], bh2[3]);
                if (full) {
                    mma16816(c[mi][0], ah[mi][0], ah[mi][1], ah[mi][2], ah[mi][3], bl[0], bl[1]);
                    mma16816(c[mi][1], ah[mi][0], ah[mi][1], ah[mi][2], ah[mi][3], bl[2], bl[3]);
                    mma16816(c[mi][2], ah[mi][0], ah[mi][1], ah[mi][2], ah[mi][3], bl2[0], bl2[1]);
                    mma16816(c[mi][3], ah[mi][0], ah[mi][1], ah[mi][2], ah[mi][3], bl2[2], bl2[3]);
                }
                mma16816(c[mi][0], al[mi][0], al[mi][1], al[mi][2], al[mi][3], bh[0], bh[1]);
                mma16816(c[mi][1], al[mi][0], al[mi][1], al[mi][2], al[mi][3], bh[2], bh[3]);
                mma16816(c[mi][2], al[mi][0], al[mi][1], al[mi][2], al[mi][3], bh2[0], bh2[1]);
                mma16816(c[mi][3], al[mi][0], al[mi][1], al[mi][2], al[mi][3], bh2[2], bh2[3]);
            }
        }

        const int colBase = cc * 64;
#pragma unroll
        for (int mi = 0; mi < 2; ++mi) {
#pragma unroll
            for (int ni = 0; ni < 4; ++ni) {
                int row0 = rowBase + warpM * 32 + mi * 16 + g;
                int col = colBase + warpN * 32 + ni * 8 + tig * 2;
                float b0 = bias[col], b1 = bias[col + 1];
#pragma unroll
                for (int rr = 0; rr < 2; ++rr) {
                    int row = row0 + rr * 8;
                    float2 val = make_float2(c[mi][ni][rr * 2] + b0, c[mi][ni][rr * 2 + 1] + b1);
                    if (MODE == 0) {
                        int b = row >> 6, n = row & 63;
                        int which = col / DIM;
                        int rem = col - which * DIM;
                        int h = rem >> 5, d = rem & 31;
                        size_t idx = ((((size_t)b * 3 + which) * HEADS + h) * NTOK + n) * HD + d;
                        *(float2*)(g_qkv + idx) = val;
                    } else {
                        *(float2*)(out + (size_t)row * DIM + col) = val;
                    }
                }
            }
        }
        __syncthreads();
    }
}

// ---------------------------------------------------------------------------
// CPB MLP
// ---------------------------------------------------------------------------
__global__ void cpb_table_kernel(const float* __restrict__ rpb,
                                 const float* __restrict__ w1,
                                 const float* __restrict__ b1,
                                 const float* __restrict__ w2)
{
    __shared__ float red[4][HEADS];
    const int p = blockIdx.x;
    const int tid = threadIdx.x;
    float r0 = rpb[p * 3 + 0], r1 = rpb[p * 3 + 1], r2 = rpb[p * 3 + 2];
    float acc[HEADS] = {};
    for (int j = tid; j < CPBH; j += 128) {
        float hv = fmaf(w1[j * 3 + 0], r0, fmaf(w1[j * 3 + 1], r1, fmaf(w1[j * 3 + 2], r2, b1[j])));
        hv = fmaxf(hv, 0.f);
#pragma unroll
        for (int h = 0; h < HEADS; ++h) acc[h] = fmaf(hv, w2[h * CPBH + j], acc[h]);
    }
#pragma unroll
    for (int h = 0; h < HEADS; ++h)
#pragma unroll
        for (int s = 16; s; s >>= 1) acc[h] += __shfl_xor_sync(~0u, acc[h], s);
    if ((tid & 31) == 0) {
#pragma unroll
        for (int h = 0; h < HEADS; ++h) red[tid >> 5][h] = acc[h];
    }
    __syncthreads();
    if (tid < HEADS)
        g_table[p * HEADS + tid] = red[0][tid] + red[1][tid] + red[2][tid] + red[3][tid];
}

// bm[w][h][ij] = 16*sigmoid(table[rpb_idx[ij]][h]) + mask[w][ij]  (fused gather)
__global__ void bm_kernel(const int* __restrict__ rpb_idx,
                          const float* __restrict__ mask)
{
    int w = blockIdx.x, h = blockIdx.y;
    const float* mp = mask + (size_t)w * NTOK * NTOK;
    float* o = g_bm + ((size_t)(w * HEADS + h)) * NTOK * NTOK;
    for (int ij = threadIdx.x; ij < NTOK * NTOK; ij += 256) {
        float t = g_table[rpb_idx[ij] * HEADS + h];
        o[ij] = 16.f / (1.f + __expf(-t)) + mp[ij];
    }
}

// ---------------------------------------------------------------------------
// tensor-core attention: 3-pass QK (softmax-protected), SINGLE-pass PV
// (P_hi x V_hi; error ~3.4e-4 direct-to-output). Output pre-split fp16 hi/lo.
// ---------------------------------------------------------------------------
#define QP  80
#define VTP 144

__global__ void __launch_bounds__(128)
attn_mma_kernel(const float* __restrict__ logit_scale)
{
    __shared__ __align__(16) char s_qhi[64 * QP], s_qlo[64 * QP];
    __shared__ __align__(16) char s_khi[64 * QP], s_klo[64 * QP];
    __shared__ __align__(16) char s_vhi[32 * VTP];

    const int b = blockIdx.x;
    const int h = blockIdx.y;
    const int tid = threadIdx.x;

    const float scale = __expf(fminf(logit_scale[h], 4.60517018599f));

    const float* qp = g_qkv + ((((size_t)b * 3 + 0) * HEADS + h) * NTOK) * HD;
    const float* kp = g_qkv + ((((size_t)b * 3 + 1) * HEADS + h) * NTOK) * HD;
    const float* vp = g_qkv + ((((size_t)b * 3 + 2) * HEADS + h) * NTOK) * HD;

    {
        const int row = tid >> 1;
        const int half = (tid & 1) * 16;

        {
            float4 f0 = *(const float4*)(qp + row * HD + half);
            float4 f1 = *(const float4*)(qp + row * HD + half + 4);
            float4 f2 = *(const float4*)(qp + row * HD + half + 8);
            float4 f3 = *(const float4*)(qp + row * HD + half + 12);
            float qv[16] = {f0.x,f0.y,f0.z,f0.w, f1.x,f1.y,f1.z,f1.w,
                            f2.x,f2.y,f2.z,f2.w, f3.x,f3.y,f3.z,f3.w};
            float ps = 0.f;
#pragma unroll
            for (int i = 0; i < 16; ++i) ps = fmaf(qv[i], qv[i], ps);
            float tot = ps + __shfl_xor_sync(~0u, ps, 1);
            float s = scale / fmaxf(sqrtf(tot), 1e-12f);
            __align__(16) __half h16[16], l16[16];
#pragma unroll
            for (int i = 0; i < 16; ++i) {
                float v = qv[i] * s;
                __half hh = __float2half_rn(v);
                h16[i] = hh;
                l16[i] = __float2half_rn(v - __half2float(hh));
            }
            *(uint4*)(s_qhi + row * QP + half * 2)      = *(uint4*)h16;
            *(uint4*)(s_qhi + row * QP + half * 2 + 16) = *(uint4*)(h16 + 8);
            *(uint4*)(s_qlo + row * QP + half * 2)      = *(uint4*)l16;
            *(uint4*)(s_qlo + row * QP + half * 2 + 16) = *(uint4*)(l16 + 8);
        }
        {
            float4 f0 = *(const float4*)(kp + row * HD + half);
            float4 f1 = *(const float4*)(kp + row * HD + half + 4);
            float4 f2 = *(const float4*)(kp + row * HD + half + 8);
            float4 f3 = *(const float4*)(kp + row * HD + half + 12);
            float kv[16] = {f0.x,f0.y,f0.z,f0.w, f1.x,f1.y,f1.z,f1.w,
                            f2.x,f2.y,f2.z,f2.w, f3.x,f3.y,f3.z,f3.w};
            float ps = 0.f;
#pragma unroll
            for (int i = 0; i < 16; ++i) ps = fmaf(kv[i], kv[i], ps);
            float tot = ps + __shfl_xor_sync(~0u, ps, 1);
            float s = 1.f / fmaxf(sqrtf(tot), 1e-12f);
            __align__(16) __half h16[16], l16[16];
#pragma unroll
            for (int i = 0; i < 16; ++i) {
                float v = kv[i] * s;
                __half hh = __float2half_rn(v);
                h16[i] = hh;
                l16[i] = __float2half_rn(v - __half2float(hh));
            }
            *(uint4*)(s_khi + row * QP + half * 2)      = *(uint4*)h16;
            *(uint4*)(s_khi + row * QP + half * 2 + 16) = *(uint4*)(h16 + 8);
            *(uint4*)(s_klo + row * QP + half * 2)      = *(uint4*)l16;
            *(uint4*)(s_klo + row * QP + half * 2 + 16) = *(uint4*)(l16 + 8);
        }
        {
            float4 f0 = *(const float4*)(vp + row * HD + half);
            float4 f1 = *(const float4*)(vp + row * HD + half + 4);
            float4 f2 = *(const float4*)(vp + row * HD + half + 8);
            float4 f3 = *(const float4*)(vp + row * HD + half + 12);
            float vv[16] = {f0.x,f0.y,f0.z,f0.w, f1.x,f1.y,f1.z,f1.w,
                            f2.x,f2.y,f2.z,f2.w, f3.x,f3.y,f3.z,f3.w};
#pragma unroll
            for (int i = 0; i < 16; ++i) {
                int d = half + i;
                *(__half*)(s_vhi + d * VTP + row * 2) = __float2half_rn(vv[i]);
            }
        }
    }
    __syncthreads();

    const int w = tid >> 5;
    const int lane = tid & 31;
    const int lrow = lane & 7;
    const int lmat = lane >> 3;
    const int g = lane >> 2;
    const int tig = lane & 3;

    // ---- QK^T: 3-pass fp16 split ----
    const uint32_t aOff = (uint32_t)((w * 16 + lrow + (lmat & 1) * 8) * QP + (lmat >> 1) * 16);
    const uint32_t bOff = (uint32_t)((lrow + (lmat >> 1) * 8) * QP + (lmat & 1) * 16);
    const uint32_t qB[3] = { smem_u32(s_qhi), smem_u32(s_qhi), smem_u32(s_qlo) };
    const uint32_t kB[3] = { smem_u32(s_khi), smem_u32(s_klo), smem_u32(s_khi) };

    float c[8][4] = {};
#pragma unroll
    for (int p = 0; p < 3; ++p) {
#pragma unroll
        for (int kt = 0; kt < 2; ++kt) {
            uint32_t a[4];
            ldsm_x4(qB[p] + aOff + kt * 32, a[0], a[1], a[2], a[3]);
#pragma unroll
            for (int nt = 0; nt < 4; ++nt) {
                uint32_t bb[4];
                ldsm_x4(kB[p] + bOff + nt * 16 * QP + kt * 32, bb[0], bb[1], bb[2], bb[3]);
                mma16816(c[nt * 2],     a[0], a[1], a[2], a[3], bb[0], bb[1]);
                mma16816(c[nt * 2 + 1], a[0], a[1], a[2], a[3], bb[2], bb[3]);
            }
        }
    }

    // ---- bias+mask, register softmax ----
    const float* bmp = g_bm + ((size_t)((b & (NW - 1)) * HEADS + h)) * NTOK * NTOK;
    const int r0 = w * 16 + g;
#pragma unroll
    for (int ni = 0; ni < 8; ++ni) {
        int col = ni * 8 + tig * 2;
        float2 b0 = *(const float2*)(bmp + r0 * NTOK + col);
        float2 b1 = *(const float2*)(bmp + (r0 + 8) * NTOK + col);
        c[ni][0] += b0.x; c[ni][1] += b0.y;
        c[ni][2] += b1.x; c[ni][3] += b1.y;
    }
    float mx0 = -3.4e38f, mx1 = -3.4e38f;
#pragma unroll
    for (int ni = 0; ni < 8; ++ni) {
        mx0 = fmaxf(mx0, fmaxf(c[ni][0], c[ni][1]));
        mx1 = fmaxf(mx1, fmaxf(c[ni][2], c[ni][3]));
    }
    mx0 = fmaxf(mx0, __shfl_xor_sync(~0u, mx0, 1));
    mx0 = fmaxf(mx0, __shfl_xor_sync(~0u, mx0, 2));
    mx1 = fmaxf(mx1, __shfl_xor_sync(~0u, mx1, 1));
    mx1 = fmaxf(mx1, __shfl_xor_sync(~0u, mx1, 2));
    float s0 = 0.f, s1 = 0.f;
#pragma unroll
    for (int ni = 0; ni < 8; ++ni) {
        c[ni][0] = __expf(c[ni][0] - mx0); s0 += c[ni][0];
        c[ni][1] = __expf(c[ni][1] - mx0); s0 += c[ni][1];
        c[ni][2] = __expf(c[ni][2] - mx1); s1 += c[ni][2];
        c[ni][3] = __expf(c[ni][3] - mx1); s1 += c[ni][3];
    }
    s0 += __shfl_xor_sync(~0u, s0, 1); s0 += __shfl_xor_sync(~0u, s0, 2);
    s1 += __shfl_xor_sync(~0u, s1, 1); s1 += __shfl_xor_sync(~0u, s1, 2);
    const float i0 = 1.f / s0, i1 = 1.f / s1;
#pragma unroll
    for (int ni = 0; ni < 8; ++ni) {
        c[ni][0] *= i0; c[ni][1] *= i0;
        c[ni][2] *= i1; c[ni][3] *= i1;
    }

    // ---- pack P as fp16 a-fragments (hi only) ----
    uint32_t aH[4][4];
#pragma unroll
    for (int kt = 0; kt < 4; ++kt) {
        const float* p0 = c[2 * kt];
        const float* p1 = c[2 * kt + 1];
        aH[kt][0] = pk_f16(p0[0], p0[1]); aH[kt][1] = pk_f16(p0[2], p0[3]);
        aH[kt][2] = pk_f16(p1[0], p1[1]); aH[kt][3] = pk_f16(p1[2], p1[3]);
    }

    // ---- PV: single pass ----
    const uint32_t vOff = (uint32_t)((lrow + (lmat >> 1) * 8) * VTP + (lmat & 1) * 16);
    const uint32_t vHiB = smem_u32(s_vhi);

    float o[4][4] = {};
#pragma unroll
    for (int kt = 0; kt < 4; ++kt) {
        uint32_t b0[4], b1[4];
        ldsm_x4(vHiB + vOff + kt * 32,            b0[0], b0[1], b0[2], b0[3]);
        ldsm_x4(vHiB + vOff + 16 * VTP + kt * 32, b1[0], b1[1], b1[2], b1[3]);
        mma16816(o[0], aH[kt][0], aH[kt][1], aH[kt][2], aH[kt][3], b0[0], b0[1]);
        mma16816(o[1], aH[kt][0], aH[kt][1], aH[kt][2], aH[kt][3], b0[2], b0[3]);
        mma16816(o[2], aH[kt][0], aH[kt][1], aH[kt][2], aH[kt][3], b1[0], b1[1]);
        mma16816(o[3], aH[kt][0], aH[kt][1], aH[kt][2], aH[kt][3], b1[2], b1[3]);
    }

    // ---- store pre-split fp16 hi/lo (heads-major concat) ----
    size_t base0 = ((size_t)b * NTOK + r0) * DIM + h * HD;
    size_t base1 = base0 + (size_t)8 * DIM;
#pragma unroll
    for (int ni = 0; ni < 4; ++ni) {
        int col = ni * 8 + tig * 2;
        float v0 = o[ni][0], v1 = o[ni][1], v2 = o[ni][2], v3 = o[ni][3];
        float h0 = __half2float(__float2half_rn(v0));
        float h1 = __half2float(__float2half_rn(v1));
        float h2 = __half2float(__float2half_rn(v2));
        float h3 = __half2float(__float2half_rn(v3));
        *(uint32_t*)(g_ahi + base0 + col) = pk_f16(v0, v1);
        *(uint32_t*)(g_alo + base0 + col) = pk_f16(v0 - h0, v1 - h1);
        *(uint32_t*)(g_ahi + base1 + col) = pk_f16(v2, v3);
        *(uint32_t*)(g_alo + base1 + col) = pk_f16(v2 - h2, v3 - h3);
    }
}

// ---------------------------------------------------------------------------
// Launch
// ---------------------------------------------------------------------------
extern "C" void kernel_launch(void* const* d_in, const int* in_sizes, int n_in,
                              void* d_out, int out_size)
{
    const float* x       = (const float*)d_in[0];
    const float* mask    = (const float*)d_in[1];
    const float* rpb     = (const float*)d_in[2];
    const int*   rpb_idx = (const int*)  d_in[3];
    const float* cpb_w1  = (const float*)d_in[4];
    const float* cpb_b1  = (const float*)d_in[5];
    const float* cpb_w2  = (const float*)d_in[6];
    const float* qkv_w   = (const float*)d_in[7];
    const float* qkv_b   = (const float*)d_in[8];
    const float* proj_w  = (const float*)d_in[9];
    const float* proj_b  = (const float*)d_in[10];
    const float* lscale  = (const float*)d_in[11];
    float* out = (float*)d_out;

    cudaFuncSetAttribute(gemm_mma_kernel<0>, cudaFuncAttributeMaxDynamicSharedMemorySize, SM_GEMM_BYTES);
    cudaFuncSetAttribute(gemm_mma_kernel<1>, cudaFuncAttributeMaxDynamicSharedMemorySize, SM_GEMM_BYTES);

    conv_w_all_kernel<<<((QKV_ELEMS + PROJ_ELEMS) / 8 + 255) / 256, 256>>>(qkv_w, proj_w);
    cpb_table_kernel<<<NPOS, 128>>>(rpb, cpb_w1, cpb_b1, cpb_w2);
    bm_kernel<<<dim3(NW, HEADS), 256>>>(rpb_idx, mask);

    gemm_mma_kernel<0><<<MROWS / 128, 256, SM_GEMM_BYTES>>>(x, qkv_b, nullptr);

    dim3 ga(BATCH, HEADS);
    attn_mma_kernel<<<ga, 128>>>(lscale);

    gemm_mma_kernel<1><<<MROWS / 128, 256, SM_GEMM_BYTES>>>(nullptr, proj_b, out);
}

// round 14
// speedup vs baseline: 1.1590x; 1.0442x over previous
#include <cuda_runtime.h>
#include <cuda_fp16.h>
#include <math.h>
#include <cstdint>

// ---------------------------------------------------------------------------
// Shapes
// ---------------------------------------------------------------------------
#define BATCH   2048
#define NTOK    64
#define DIM     192
#define HEADS   6
#define HD      32
#define QKVC    576
#define NPOS    343
#define CPBH    512
#define NW      64
#define MROWS   (BATCH * NTOK)      // 131072

// ---------------------------------------------------------------------------
// Scratch (device-code-only references!)
// ---------------------------------------------------------------------------
__device__ float g_qkv[(size_t)BATCH * 3 * HEADS * NTOK * HD];
__device__ __align__(16) __half g_ahi[(size_t)MROWS * DIM];
__device__ __align__(16) __half g_alo[(size_t)MROWS * DIM];
__device__ __align__(16) __half g_wqh[QKVC * DIM];
__device__ __align__(16) __half g_wql[QKVC * DIM];
__device__ __align__(16) __half g_wph[DIM * DIM];
__device__ __align__(16) __half g_wpl[DIM * DIM];
__device__ float g_table[NPOS * HEADS];
__device__ float g_bm[(size_t)NW * HEADS * NTOK * NTOK];

// ---------------------------------------------------------------------------
// helpers
// ---------------------------------------------------------------------------
__device__ __forceinline__ uint32_t smem_u32(const void* p) {
    uint32_t a;
    asm("{ .reg .u64 t; cvta.to.shared.u64 t, %1; cvt.u32.u64 %0, t; }" : "=r"(a) : "l"(p));
    return a;
}
__device__ __forceinline__ void ldsm_x4(uint32_t addr, uint32_t& r0, uint32_t& r1,
                                        uint32_t& r2, uint32_t& r3) {
    asm volatile("ldmatrix.sync.aligned.m8n8.x4.shared.b16 {%0,%1,%2,%3}, [%4];"
                 : "=r"(r0), "=r"(r1), "=r"(r2), "=r"(r3) : "r"(addr));
}
__device__ __forceinline__ void mma16816(float* c, uint32_t a0, uint32_t a1,
                                         uint32_t a2, uint32_t a3,
                                         uint32_t b0, uint32_t b1) {
    asm volatile("mma.sync.aligned.m16n8k16.row.col.f32.f16.f16.f32 "
                 "{%0,%1,%2,%3}, {%4,%5,%6,%7}, {%8,%9}, {%0,%1,%2,%3};"
                 : "+f"(c[0]), "+f"(c[1]), "+f"(c[2]), "+f"(c[3])
                 : "r"(a0), "r"(a1), "r"(a2), "r"(a3), "r"(b0), "r"(b1));
}
__device__ __forceinline__ uint32_t pk_f16(float x0, float x1) {
    __half2 t = __floats2half2_rn(x0, x1);
    return *(uint32_t*)&t;
}
__device__ __forceinline__ void cp_async16(uint32_t dst, const void* src) {
    asm volatile("cp.async.ca.shared.global [%0], [%1], 16;"
                 :: "r"(dst), "l"(src) : "memory");
}
__device__ __forceinline__ void cp_commit() {
    asm volatile("cp.async.commit_group;" ::: "memory");
}
template <int N>
__device__ __forceinline__ void cp_wait() {
    asm volatile("cp.async.wait_group %0;" :: "n"(N) : "memory");
}

// ---------------------------------------------------------------------------
// merged weight split-conversion
// ---------------------------------------------------------------------------
#define QKV_ELEMS (QKVC * DIM)
#define PROJ_ELEMS (DIM * DIM)
__global__ void conv_w_all_kernel(const float* __restrict__ qkv_w,
                                  const float* __restrict__ proj_w)
{
    int base = (blockIdx.x * blockDim.x + threadIdx.x) * 8;
    const float* src;
    __half *hi, *lo;
    if (base < QKV_ELEMS) {
        src = qkv_w; hi = g_wqh; lo = g_wql;
    } else {
        base -= QKV_ELEMS;
        if (base >= PROJ_ELEMS) return;
        src = proj_w; hi = g_wph; lo = g_wpl;
    }
    float4 v0 = *(const float4*)(src + base);
    float4 v1 = *(const float4*)(src + base + 4);
    float v[8] = {v0.x, v0.y, v0.z, v0.w, v1.x, v1.y, v1.z, v1.w};
    __align__(16) __half h8[8], l8[8];
#pragma unroll
    for (int i = 0; i < 8; ++i) {
        __half h = __float2half_rn(v[i]);
        h8[i] = h;
        l8[i] = __float2half_rn(v[i] - __half2float(h));
    }
    *(uint4*)(hi + base) = *(uint4*)h8;
    *(uint4*)(lo + base) = *(uint4*)l8;
}

// ---------------------------------------------------------------------------
// GEMM with software-pipelined inner loop (double-buffered register frags).
// 128-row CTA, 8 warps (4Mx2N), A-resident, cp.async double-buffered B.
// MODE 0 (QKV): chunks 0-5 3-pass; 6-8 2-pass.  MODE 1 (proj): all 2-pass.
// ---------------------------------------------------------------------------
#define PITCHB 400
#define SM_AHI 0
#define SM_ALO (128 * PITCHB)
#define SM_B   (2 * 128 * PITCHB)
#define SM_BUFSZ (2 * 64 * PITCHB)
#define SM_BLO_OFF (64 * PITCHB)
#define SM_GEMM_BYTES (SM_B + 2 * SM_BUFSZ)   // 204800

struct Frag {
    uint32_t ah[2][4], al[2][4];
    uint32_t bh[4], bh2[4], bl[4], bl2[4];
};

template <bool FULL>
__device__ __forceinline__ void frag_load(int k, Frag& f,
                                          uint32_t aHiB, uint32_t aLoB,
                                          uint32_t bHiT, uint32_t bLoT)
{
    ldsm_x4(aHiB + k * 32,               f.ah[0][0], f.ah[0][1], f.ah[0][2], f.ah[0][3]);
    ldsm_x4(aHiB + 16 * PITCHB + k * 32, f.ah[1][0], f.ah[1][1], f.ah[1][2], f.ah[1][3]);
    ldsm_x4(aLoB + k * 32,               f.al[0][0], f.al[0][1], f.al[0][2], f.al[0][3]);
    ldsm_x4(aLoB + 16 * PITCHB + k * 32, f.al[1][0], f.al[1][1], f.al[1][2], f.al[1][3]);
    ldsm_x4(bHiT + k * 32,               f.bh[0], f.bh[1], f.bh[2], f.bh[3]);
    ldsm_x4(bHiT + 16 * PITCHB + k * 32, f.bh2[0], f.bh2[1], f.bh2[2], f.bh2[3]);
    if (FULL) {
        ldsm_x4(bLoT + k * 32,               f.bl[0], f.bl[1], f.bl[2], f.bl[3]);
        ldsm_x4(bLoT + 16 * PITCHB + k * 32, f.bl2[0], f.bl2[1], f.bl2[2], f.bl2[3]);
    }
}

template <bool FULL>
__device__ __forceinline__ void frag_mma(const Frag& f, float (&c)[2][4][4])
{
#pragma unroll
    for (int mi = 0; mi < 2; ++mi) {
        mma16816(c[mi][0], f.ah[mi][0], f.ah[mi][1], f.ah[mi][2], f.ah[mi][3], f.bh[0], f.bh[1]);
        mma16816(c[mi][1], f.ah[mi][0], f.ah[mi][1], f.ah[mi][2], f.ah[mi][3], f.bh[2], f.bh[3]);
        mma16816(c[mi][2], f.ah[mi][0], f.ah[mi][1], f.ah[mi][2], f.ah[mi][3], f.bh2[0], f.bh2[1]);
        mma16816(c[mi][3], f.ah[mi][0], f.ah[mi][1], f.ah[mi][2], f.ah[mi][3], f.bh2[2], f.bh2[3]);
        if (FULL) {
            mma16816(c[mi][0], f.ah[mi][0], f.ah[mi][1], f.ah[mi][2], f.ah[mi][3], f.bl[0], f.bl[1]);
            mma16816(c[mi][1], f.ah[mi][0], f.ah[mi][1], f.ah[mi][2], f.ah[mi][3], f.bl[2], f.bl[3]);
            mma16816(c[mi][2], f.ah[mi][0], f.ah[mi][1], f.ah[mi][2], f.ah[mi][3], f.bl2[0], f.bl2[1]);
            mma16816(c[mi][3], f.ah[mi][0], f.ah[mi][1], f.ah[mi][2], f.ah[mi][3], f.bl2[2], f.bl2[3]);
        }
        mma16816(c[mi][0], f.al[mi][0], f.al[mi][1], f.al[mi][2], f.al[mi][3], f.bh[0], f.bh[1]);
        mma16816(c[mi][1], f.al[mi][0], f.al[mi][1], f.al[mi][2], f.al[mi][3], f.bh[2], f.bh[3]);
        mma16816(c[mi][2], f.al[mi][0], f.al[mi][1], f.al[mi][2], f.al[mi][3], f.bh2[0], f.bh2[1]);
        mma16816(c[mi][3], f.al[mi][0], f.al[mi][1], f.al[mi][2], f.al[mi][3], f.bh2[2], f.bh2[3]);
    }
}

template <bool FULL>
__device__ __forceinline__ void run_chunk(uint32_t aHiB, uint32_t aLoB,
                                          uint32_t bHiT, uint32_t bLoT,
                                          float (&c)[2][4][4])
{
    Frag f0, f1;
    frag_load<FULL>(0, f0, aHiB, aLoB, bHiT, bLoT);
#pragma unroll
    for (int k = 0; k < 12; ++k) {
        Frag& cur = (k & 1) ? f1 : f0;
        Frag& nxt = (k & 1) ? f0 : f1;
        if (k < 11) frag_load<FULL>(k + 1, nxt, aHiB, aLoB, bHiT, bLoT);
        frag_mma<FULL>(cur, c);
    }
}

template <int MODE>
__global__ void __launch_bounds__(256, 1)
gemm_mma_kernel(const float* __restrict__ Ain,
                const float* __restrict__ bias, float* __restrict__ out)
{
    constexpr int NC = (MODE == 0) ? 9 : 3;
    const __half* __restrict__ Whi = (MODE == 0) ? g_wqh : g_wph;
    const __half* __restrict__ Wlo = (MODE == 0) ? g_wql : g_wpl;

    extern __shared__ __align__(16) char sm[];
    const int tid = threadIdx.x;
    const int wid = tid >> 5;
    const int lane = tid & 31;
    const int rowBase = blockIdx.x * 128;
    const uint32_t smBase = smem_u32(sm);

    // ---- prefetch B chunk 0 ----
    {
        const bool fullNext = (MODE == 0);
        const uint32_t dBase = smBase + SM_B;
#pragma unroll
        for (int i = tid; i < 64 * 24; i += 256) {
            int r = i / 24, c = i % 24;
            size_t gg = (size_t)r * DIM + c * 8;
            uint32_t d = dBase + r * PITCHB + c * 16;
            cp_async16(d, Whi + gg);
            if (fullNext) cp_async16(d + SM_BLO_OFF, Wlo + gg);
        }
        cp_commit();
    }

    // ---- load A ----
    if (MODE == 0) {
#pragma unroll
        for (int i = tid; i < 128 * 48; i += 256) {
            int r = i / 48, c4 = i % 48;
            float4 v = *(const float4*)(Ain + (size_t)(rowBase + r) * DIM + c4 * 4);
            float vv[4] = {v.x, v.y, v.z, v.w};
            __align__(8) __half h4[4], l4[4];
#pragma unroll
            for (int q = 0; q < 4; ++q) {
                __half h = __float2half_rn(vv[q]);
                h4[q] = h;
                l4[q] = __float2half_rn(vv[q] - __half2float(h));
            }
            *(uint2*)(sm + SM_AHI + r * PITCHB + c4 * 8) = *(uint2*)h4;
            *(uint2*)(sm + SM_ALO + r * PITCHB + c4 * 8) = *(uint2*)l4;
        }
    } else {
#pragma unroll
        for (int i = tid; i < 128 * 24; i += 256) {
            int r = i / 24, c = i % 24;
            size_t gg = (size_t)(rowBase + r) * DIM + c * 8;
            cp_async16(smBase + SM_AHI + r * PITCHB + c * 16, g_ahi + gg);
            cp_async16(smBase + SM_ALO + r * PITCHB + c * 16, g_alo + gg);
        }
        cp_commit();
    }

    const int warpM = wid >> 1;
    const int warpN = wid & 1;
    const int lrow = lane & 7;
    const int lmat = lane >> 3;

    const uint32_t aOff = (uint32_t)((warpM * 32 + lrow + (lmat & 1) * 8) * PITCHB
                                     + (lmat >> 1) * 16);
    const uint32_t bOff = (uint32_t)((warpN * 32 + lrow + (lmat >> 1) * 8) * PITCHB
                                     + (lmat & 1) * 16);
    const uint32_t aHiB = smBase + SM_AHI + aOff;
    const uint32_t aLoB = smBase + SM_ALO + aOff;
    const int g = lane >> 2, tig = lane & 3;

    for (int cc = 0; cc < NC; ++cc) {
        const int cur = cc & 1;
        const bool full = (MODE == 0) && (cc < 6);
        if (cc + 1 < NC) {
            const bool fullNext = (MODE == 0) && (cc + 1 < 6);
            const uint32_t dBase = smBase + SM_B + (1 - cur) * SM_BUFSZ;
            const int colN = (cc + 1) * 64;
#pragma unroll
            for (int i = tid; i < 64 * 24; i += 256) {
                int r = i / 24, c = i % 24;
                size_t gg = (size_t)(colN + r) * DIM + c * 8;
                uint32_t d = dBase + r * PITCHB + c * 16;
                cp_async16(d, Whi + gg);
                if (fullNext) cp_async16(d + SM_BLO_OFF, Wlo + gg);
            }
            cp_commit();
            cp_wait<1>();
        } else {
            cp_wait<0>();
        }
        __syncthreads();

        const uint32_t bHiT = smBase + SM_B + cur * SM_BUFSZ + bOff;
        const uint32_t bLoT = bHiT + SM_BLO_OFF;

        float c[2][4][4] = {};
        if (full) run_chunk<true>(aHiB, aLoB, bHiT, bLoT, c);
        else      run_chunk<false>(aHiB, aLoB, bHiT, bLoT, c);

        const int colBase = cc * 64;
#pragma unroll
        for (int mi = 0; mi < 2; ++mi) {
#pragma unroll
            for (int ni = 0; ni < 4; ++ni) {
                int row0 = rowBase + warpM * 32 + mi * 16 + g;
                int col = colBase + warpN * 32 + ni * 8 + tig * 2;
                float b0 = bias[col], b1 = bias[col + 1];
#pragma unroll
                for (int rr = 0; rr < 2; ++rr) {
                    int row = row0 + rr * 8;
                    float2 val = make_float2(c[mi][ni][rr * 2] + b0, c[mi][ni][rr * 2 + 1] + b1);
                    if (MODE == 0) {
                        int b = row >> 6, n = row & 63;
                        int which = col / DIM;
                        int rem = col - which * DIM;
                        int h = rem >> 5, d = rem & 31;
                        size_t idx = ((((size_t)b * 3 + which) * HEADS + h) * NTOK + n) * HD + d;
                        *(float2*)(g_qkv + idx) = val;
                    } else {
                        *(float2*)(out + (size_t)row * DIM + col) = val;
                    }
                }
            }
        }
        __syncthreads();
    }
}

// ---------------------------------------------------------------------------
// CPB MLP + fused bias/mask gather
// ---------------------------------------------------------------------------
__global__ void cpb_table_kernel(const float* __restrict__ rpb,
                                 const float* __restrict__ w1,
                                 const float* __restrict__ b1,
                                 const float* __restrict__ w2)
{
    __shared__ float red[4][HEADS];
    const int p = blockIdx.x;
    const int tid = threadIdx.x;
    float r0 = rpb[p * 3 + 0], r1 = rpb[p * 3 + 1], r2 = rpb[p * 3 + 2];
    float acc[HEADS] = {};
    for (int j = tid; j < CPBH; j += 128) {
        float hv = fmaf(w1[j * 3 + 0], r0, fmaf(w1[j * 3 + 1], r1, fmaf(w1[j * 3 + 2], r2, b1[j])));
        hv = fmaxf(hv, 0.f);
#pragma unroll
        for (int h = 0; h < HEADS; ++h) acc[h] = fmaf(hv, w2[h * CPBH + j], acc[h]);
    }
#pragma unroll
    for (int h = 0; h < HEADS; ++h)
#pragma unroll
        for (int s = 16; s; s >>= 1) acc[h] += __shfl_xor_sync(~0u, acc[h], s);
    if ((tid & 31) == 0) {
#pragma unroll
        for (int h = 0; h < HEADS; ++h) red[tid >> 5][h] = acc[h];
    }
    __syncthreads();
    if (tid < HEADS)
        g_table[p * HEADS + tid] = red[0][tid] + red[1][tid] + red[2][tid] + red[3][tid];
}

__global__ void bm_kernel(const int* __restrict__ rpb_idx,
                          const float* __restrict__ mask)
{
    int w = blockIdx.x, h = blockIdx.y;
    const float* mp = mask + (size_t)w * NTOK * NTOK;
    float* o = g_bm + ((size_t)(w * HEADS + h)) * NTOK * NTOK;
    for (int ij = threadIdx.x; ij < NTOK * NTOK; ij += 256) {
        float t = g_table[rpb_idx[ij] * HEADS + h];
        o[ij] = 16.f / (1.f + __expf(-t)) + mp[ij];
    }
}

// ---------------------------------------------------------------------------
// tensor-core attention: 3-pass QK, single-pass PV; pre-split fp16 output
// ---------------------------------------------------------------------------
#define QP  80
#define VTP 144

__global__ void __launch_bounds__(128)
attn_mma_kernel(const float* __restrict__ logit_scale)
{
    __shared__ __align__(16) char s_qhi[64 * QP], s_qlo[64 * QP];
    __shared__ __align__(16) char s_khi[64 * QP], s_klo[64 * QP];
    __shared__ __align__(16) char s_vhi[32 * VTP];

    const int b = blockIdx.x;
    const int h = blockIdx.y;
    const int tid = threadIdx.x;

    const float scale = __expf(fminf(logit_scale[h], 4.60517018599f));

    const float* qp = g_qkv + ((((size_t)b * 3 + 0) * HEADS + h) * NTOK) * HD;
    const float* kp = g_qkv + ((((size_t)b * 3 + 1) * HEADS + h) * NTOK) * HD;
    const float* vp = g_qkv + ((((size_t)b * 3 + 2) * HEADS + h) * NTOK) * HD;

    {
        const int row = tid >> 1;
        const int half = (tid & 1) * 16;

        {
            float4 f0 = *(const float4*)(qp + row * HD + half);
            float4 f1 = *(const float4*)(qp + row * HD + half + 4);
            float4 f2 = *(const float4*)(qp + row * HD + half + 8);
            float4 f3 = *(const float4*)(qp + row * HD + half + 12);
            float qv[16] = {f0.x,f0.y,f0.z,f0.w, f1.x,f1.y,f1.z,f1.w,
                            f2.x,f2.y,f2.z,f2.w, f3.x,f3.y,f3.z,f3.w};
            float ps = 0.f;
#pragma unroll
            for (int i = 0; i < 16; ++i) ps = fmaf(qv[i], qv[i], ps);
            float tot = ps + __shfl_xor_sync(~0u, ps, 1);
            float s = scale / fmaxf(sqrtf(tot), 1e-12f);
            __align__(16) __half h16[16], l16[16];
#pragma unroll
            for (int i = 0; i < 16; ++i) {
                float v = qv[i] * s;
                __half hh = __float2half_rn(v);
                h16[i] = hh;
                l16[i] = __float2half_rn(v - __half2float(hh));
            }
            *(uint4*)(s_qhi + row * QP + half * 2)      = *(uint4*)h16;
            *(uint4*)(s_qhi + row * QP + half * 2 + 16) = *(uint4*)(h16 + 8);
            *(uint4*)(s_qlo + row * QP + half * 2)      = *(uint4*)l16;
            *(uint4*)(s_qlo + row * QP + half * 2 + 16) = *(uint4*)(l16 + 8);
        }
        {
            float4 f0 = *(const float4*)(kp + row * HD + half);
            float4 f1 = *(const float4*)(kp + row * HD + half + 4);
            float4 f2 = *(const float4*)(kp + row * HD + half + 8);
            float4 f3 = *(const float4*)(kp + row * HD + half + 12);
            float kv[16] = {f0.x,f0.y,f0.z,f0.w, f1.x,f1.y,f1.z,f1.w,
                            f2.x,f2.y,f2.z,f2.w, f3.x,f3.y,f3.z,f3.w};
            float ps = 0.f;
#pragma unroll
            for (int i = 0; i < 16; ++i) ps = fmaf(kv[i], kv[i], ps);
            float tot = ps + __shfl_xor_sync(~0u, ps, 1);
            float s = 1.f / fmaxf(sqrtf(tot), 1e-12f);
            __align__(16) __half h16[16], l16[16];
#pragma unroll
            for (int i = 0; i < 16; ++i) {
                float v = kv[i] * s;
                __half hh = __float2half_rn(v);
                h16[i] = hh;
                l16[i] = __float2half_rn(v - __half2float(hh));
            }
            *(uint4*)(s_khi + row * QP + half * 2)      = *(uint4*)h16;
            *(uint4*)(s_khi + row * QP + half * 2 + 16) = *(uint4*)(h16 + 8);
            *(uint4*)(s_klo + row * QP + half * 2)      = *(uint4*)l16;
            *(uint4*)(s_klo + row * QP + half * 2 + 16) = *(uint4*)(l16 + 8);
        }
        {
            float4 f0 = *(const float4*)(vp + row * HD + half);
            float4 f1 = *(const float4*)(vp + row * HD + half + 4);
            float4 f2 = *(const float4*)(vp + row * HD + half + 8);
            float4 f3 = *(const float4*)(vp + row * HD + half + 12);
            float vv[16] = {f0.x,f0.y,f0.z,f0.w, f1.x,f1.y,f1.z,f1.w,
                            f2.x,f2.y,f2.z,f2.w, f3.x,f3.y,f3.z,f3.w};
#pragma unroll
            for (int i = 0; i < 16; ++i) {
                int d = half + i;
                *(__half*)(s_vhi + d * VTP + row * 2) = __float2half_rn(vv[i]);
            }
        }
    }
    __syncthreads();

    const int w = tid >> 5;
    const int lane = tid & 31;
    const int lrow = lane & 7;
    const int lmat = lane >> 3;
    const int g = lane >> 2;
    const int tig = lane & 3;

    const uint32_t aOff = (uint32_t)((w * 16 + lrow + (lmat & 1) * 8) * QP + (lmat >> 1) * 16);
    const uint32_t bOff = (uint32_t)((lrow + (lmat >> 1) * 8) * QP + (lmat & 1) * 16);
    const uint32_t qB[3] = { smem_u32(s_qhi), smem_u32(s_qhi), smem_u32(s_qlo) };
    const uint32_t kB[3] = { smem_u32(s_khi), smem_u32(s_klo), smem_u32(s_khi) };

    float c[8][4] = {};
#pragma unroll
    for (int p = 0; p < 3; ++p) {
#pragma unroll
        for (int kt = 0; kt < 2; ++kt) {
            uint32_t a[4];
            ldsm_x4(qB[p] + aOff + kt * 32, a[0], a[1], a[2], a[3]);
#pragma unroll
            for (int nt = 0; nt < 4; ++nt) {
                uint32_t bb[4];
                ldsm_x4(kB[p] + bOff + nt * 16 * QP + kt * 32, bb[0], bb[1], bb[2], bb[3]);
                mma16816(c[nt * 2],     a[0], a[1], a[2], a[3], bb[0], bb[1]);
                mma16816(c[nt * 2 + 1], a[0], a[1], a[2], a[3], bb[2], bb[3]);
            }
        }
    }

    const float* bmp = g_bm + ((size_t)((b & (NW - 1)) * HEADS + h)) * NTOK * NTOK;
    const int r0 = w * 16 + g;
#pragma unroll
    for (int ni = 0; ni < 8; ++ni) {
        int col = ni * 8 + tig * 2;
        float2 b0 = *(const float2*)(bmp + r0 * NTOK + col);
        float2 b1 = *(const float2*)(bmp + (r0 + 8) * NTOK + col);
        c[ni][0] += b0.x; c[ni][1] += b0.y;
        c[ni][2] += b1.x; c[ni][3] += b1.y;
    }
    float mx0 = -3.4e38f, mx1 = -3.4e38f;
#pragma unroll
    for (int ni = 0; ni < 8; ++ni) {
        mx0 = fmaxf(mx0, fmaxf(c[ni][0], c[ni][1]));
        mx1 = fmaxf(mx1, fmaxf(c[ni][2], c[ni][3]));
    }
    mx0 = fmaxf(mx0, __shfl_xor_sync(~0u, mx0, 1));
    mx0 = fmaxf(mx0, __shfl_xor_sync(~0u, mx0, 2));
    mx1 = fmaxf(mx1, __shfl_xor_sync(~0u, mx1, 1));
    mx1 = fmaxf(mx1, __shfl_xor_sync(~0u, mx1, 2));
    float s0 = 0.f, s1 = 0.f;
#pragma unroll
    for (int ni = 0; ni < 8; ++ni) {
        c[ni][0] = __expf(c[ni][0] - mx0); s0 += c[ni][0];
        c[ni][1] = __expf(c[ni][1] - mx0); s0 += c[ni][1];
        c[ni][2] = __expf(c[ni][2] - mx1); s1 += c[ni][2];
        c[ni][3] = __expf(c[ni][3] - mx1); s1 += c[ni][3];
    }
    s0 += __shfl_xor_sync(~0u, s0, 1); s0 += __shfl_xor_sync(~0u, s0, 2);
    s1 += __shfl_xor_sync(~0u, s1, 1); s1 += __shfl_xor_sync(~0u, s1, 2);
    const float i0 = 1.f / s0, i1 = 1.f / s1;
#pragma unroll
    for (int ni = 0; ni < 8; ++ni) {
        c[ni][0] *= i0; c[ni][1] *= i0;
        c[ni][2] *= i1; c[ni][3] *= i1;
    }

    uint32_t aH[4][4];
#pragma unroll
    for (int kt = 0; kt < 4; ++kt) {
        const float* p0 = c[2 * kt];
        const float* p1 = c[2 * kt + 1];
        aH[kt][0] = pk_f16(p0[0], p0[1]); aH[kt][1] = pk_f16(p0[2], p0[3]);
        aH[kt][2] = pk_f16(p1[0], p1[1]); aH[kt][3] = pk_f16(p1[2], p1[3]);
    }

    const uint32_t vOff = (uint32_t)((lrow + (lmat >> 1) * 8) * VTP + (lmat & 1) * 16);
    const uint32_t vHiB = smem_u32(s_vhi);

    float o[4][4] = {};
#pragma unroll
    for (int kt = 0; kt < 4; ++kt) {
        uint32_t b0[4], b1[4];
        ldsm_x4(vHiB + vOff + kt * 32,            b0[0], b0[1], b0[2], b0[3]);
        ldsm_x4(vHiB + vOff + 16 * VTP + kt * 32, b1[0], b1[1], b1[2], b1[3]);
        mma16816(o[0], aH[kt][0], aH[kt][1], aH[kt][2], aH[kt][3], b0[0], b0[1]);
        mma16816(o[1], aH[kt][0], aH[kt][1], aH[kt][2], aH[kt][3], b0[2], b0[3]);
        mma16816(o[2], aH[kt][0], aH[kt][1], aH[kt][2], aH[kt][3], b1[0], b1[1]);
        mma16816(o[3], aH[kt][0], aH[kt][1], aH[kt][2], aH[kt][3], b1[2], b1[3]);
    }

    size_t base0 = ((size_t)b * NTOK + r0) * DIM + h * HD;
    size_t base1 = base0 + (size_t)8 * DIM;
#pragma unroll
    for (int ni = 0; ni < 4; ++ni) {
        int col = ni * 8 + tig * 2;
        float v0 = o[ni][0], v1 = o[ni][1], v2 = o[ni][2], v3 = o[ni][3];
        float h0 = __half2float(__float2half_rn(v0));
        float h1 = __half2float(__float2half_rn(v1));
        float h2 = __half2float(__float2half_rn(v2));
        float h3 = __half2float(__float2half_rn(v3));
        *(uint32_t*)(g_ahi + base0 + col) = pk_f16(v0, v1);
        *(uint32_t*)(g_alo + base0 + col) = pk_f16(v0 - h0, v1 - h1);
        *(uint32_t*)(g_ahi + base1 + col) = pk_f16(v2, v3);
        *(uint32_t*)(g_alo + base1 + col) = pk_f16(v2 - h2, v3 - h3);
    }
}

// ---------------------------------------------------------------------------
// Launch
// ---------------------------------------------------------------------------
extern "C" void kernel_launch(void* const* d_in, const int* in_sizes, int n_in,
                              void* d_out, int out_size)
{
    const float* x       = (const float*)d_in[0];
    const float* mask    = (const float*)d_in[1];
    const float* rpb     = (const float*)d_in[2];
    const int*   rpb_idx = (const int*)  d_in[3];
    const float* cpb_w1  = (const float*)d_in[4];
    const float* cpb_b1  = (const float*)d_in[5];
    const float* cpb_w2  = (const float*)d_in[6];
    const float* qkv_w   = (const float*)d_in[7];
    const float* qkv_b   = (const float*)d_in[8];
    const float* proj_w  = (const float*)d_in[9];
    const float* proj_b  = (const float*)d_in[10];
    const float* lscale  = (const float*)d_in[11];
    float* out = (float*)d_out;

    cudaFuncSetAttribute(gemm_mma_kernel<0>, cudaFuncAttributeMaxDynamicSharedMemorySize, SM_GEMM_BYTES);
    cudaFuncSetAttribute(gemm_mma_kernel<1>, cudaFuncAttributeMaxDynamicSharedMemorySize, SM_GEMM_BYTES);

    conv_w_all_kernel<<<((QKV_ELEMS + PROJ_ELEMS) / 8 + 255) / 256, 256>>>(qkv_w, proj_w);
    cpb_table_kernel<<<NPOS, 128>>>(rpb, cpb_w1, cpb_b1, cpb_w2);
    bm_kernel<<<dim3(NW, HEADS), 256>>>(rpb_idx, mask);

    gemm_mma_kernel<0><<<MROWS / 128, 256, SM_GEMM_BYTES>>>(x, qkv_b, nullptr);

    dim3 ga(BATCH, HEADS);
    attn_mma_kernel<<<ga, 128>>>(lscale);

    gemm_mma_kernel<1><<<MROWS / 128, 256, SM_GEMM_BYTES>>>(nullptr, proj_b, out);
}